// round 1
// baseline (speedup 1.0000x reference)
#include <cuda_runtime.h>
#include <cuda_bf16.h>
#include <cstdint>

#define NPTS 131072
#define BSEG 16
#define EPSF 1e-5f

// ---------------- scratch (__device__ globals: allocation-free) ----------------
__device__ float d_h  [128 * NPTS];   // relu(bn1(W1 x))
__device__ float d_f  [256 * NPTS];   // bn2(W2 h)
__device__ float d_h3 [512 * NPTS];   // relu(bn3(W3 xc))
__device__ float d_W1t[3   * 128];    // folded, transposed [k][c]
__device__ float d_b1f[128];
__device__ float d_W2t[128 * 256];
__device__ float d_b2f[256];
__device__ float d_W3bt[256 * 512];   // only cols 256..511 of W3 (f part)
__device__ float d_b3f[512];
__device__ float d_u  [512 * BSEG];   // W3a' @ g^T  (per-segment bias)
__device__ float d_W4t[512 * 1024];
__device__ float d_b4f[1024];
__device__ unsigned d_gkey[BSEG * 256];
__device__ float    d_gf  [BSEG * 256];
__device__ unsigned d_vkey[BSEG * 1024];
__device__ int d_seg [NPTS];
__device__ int d_offs[BSEG + 1];

// monotonic float<->uint keys for atomicMax-based float max
__device__ __forceinline__ unsigned f2key(float f) {
    unsigned u = __float_as_uint(f);
    return (u & 0x80000000u) ? ~u : (u | 0x80000000u);
}
__device__ __forceinline__ float key2f(unsigned k) {
    return (k & 0x80000000u) ? __uint_as_float(k & 0x7FFFFFFFu)
                             : __uint_as_float(~k);
}

// ---------------- small setup kernels ----------------
__global__ void init_keys_kernel() {
    int i = blockIdx.x * blockDim.x + threadIdx.x;
    if (i < BSEG * 256)  d_gkey[i] = 0u;
    if (i < BSEG * 1024) d_vkey[i] = 0u;
}

// fold BN into weights: Wt[k*C+c] = s[c]*W[c][KOFF+k], bf[c] = s*b + be - s*m
template<int L>
__global__ void prep_kernel(const float* __restrict__ W, const float* __restrict__ b,
                            const float* __restrict__ g, const float* __restrict__ be,
                            const float* __restrict__ m, const float* __restrict__ v) {
    constexpr int C    = (L==1)?128:(L==2)?256:(L==3)?512:1024;
    constexpr int KOUT = (L==1)?3  :(L==2)?128:(L==3)?256:512;
    constexpr int KSRC = (L==1)?3  :(L==2)?128:512;
    constexpr int KOFF = (L==3)?256:0;
    float* Wt = (L==1)?d_W1t:(L==2)?d_W2t:(L==3)?d_W3bt:d_W4t;
    float* bf = (L==1)?d_b1f:(L==2)?d_b2f:(L==3)?d_b3f:d_b4f;
    const int stride = gridDim.x * blockDim.x;
    const int t0 = blockIdx.x * blockDim.x + threadIdx.x;
    for (int i = t0; i < C; i += stride) {
        float s = g[i] * rsqrtf(v[i] + EPSF);
        bf[i] = s * b[i] + be[i] - s * m[i];
    }
    for (int idx = t0; idx < C * KOUT; idx += stride) {
        int k = idx / C, c = idx % C;
        float s = g[c] * rsqrtf(v[c] + EPSF);
        Wt[idx] = s * W[c * KSRC + KOFF + k];
    }
}

__global__ void compute_offs_kernel(const int* __restrict__ npts) {
    if (threadIdx.x == 0 && blockIdx.x == 0) {
        int a = 0;
        for (int s = 0; s < BSEG; s++) { d_offs[s] = a; a += npts[s]; }
        d_offs[BSEG] = a;
    }
}

__global__ void fill_seg_kernel() {
    int j = blockIdx.x * blockDim.x + threadIdx.x;
    if (j < NPTS) {
        int s = 0;
        #pragma unroll
        for (int t = 1; t < BSEG; t++) if (j >= d_offs[t]) s = t;
        d_seg[j] = s;
    }
}

// layer1: h = relu(W1' x + b1'), K=3 trivial
__global__ void k_h_kernel(const float* __restrict__ x) {
    int idx = blockIdx.x * blockDim.x + threadIdx.x;  // over 128*NPTS
    int c = idx / NPTS;
    int j = idx - c * NPTS;
    float val = d_b1f[c]
              + d_W1t[0 * 128 + c] * x[j]
              + d_W1t[1 * 128 + c] * x[NPTS + j]
              + d_W1t[2 * 128 + c] * x[2 * NPTS + j];
    d_h[idx] = fmaxf(val, 0.0f);
}

__global__ void fin_g_kernel() {
    int i = blockIdx.x * blockDim.x + threadIdx.x;
    if (i < BSEG * 256) d_gf[i] = key2f(d_gkey[i]);
}

// u[m][s] = s3[m] * sum_{r<256} W3[m][r] * g[s][r]
__global__ void k_u_kernel(const float* __restrict__ W3,
                           const float* __restrict__ g3,
                           const float* __restrict__ v3) {
    int idx = blockIdx.x * blockDim.x + threadIdx.x;  // 512*16
    if (idx >= 512 * BSEG) return;
    int m = idx >> 4, s = idx & 15;
    float sc = g3[m] * rsqrtf(v3[m] + EPSF);
    float acc = 0.0f;
    for (int r = 0; r < 256; r++)
        acc += W3[m * 512 + r] * d_gf[s * 256 + r];
    d_u[m * BSEG + s] = sc * acc;
}

__global__ void fin_v_kernel(float* __restrict__ out) {
    int i = blockIdx.x * blockDim.x + threadIdx.x;
    if (i < BSEG * 1024) out[i] = key2f(d_vkey[i]);
}

// ---------------- the SGEMM workhorse ----------------
// C[M][NPTS] = Wt[K][M]^T applied to Xin[K][NPTS], + bias, (+u[m][seg]), (relu),
// (write C), (segment-max -> keybuf).
// Block tile 128x128, 256 threads, 8x8 per thread, K-chunk 8.
// CFG0: f  = W2t @ h   (M=256,K=128, write + segmax->gkey)
// CFG1: h3 = relu(W3bt @ f + u[seg]) (M=512,K=256, write)
// CFG2: v  = segmax(W4t @ h3)        (M=1024,K=512, segmax->vkey only)
template<int CFG>
__global__ void __launch_bounds__(256)
gemm_kernel() {
    constexpr int  M      = (CFG==0)?256:(CFG==1)?512:1024;
    constexpr int  K      = (CFG==0)?128:(CFG==1)?256:512;
    constexpr bool RELU   = (CFG==1);
    constexpr bool ADDU   = (CFG==1);
    constexpr bool WRITE  = (CFG!=2);
    constexpr bool SEGMAX = (CFG!=1);

    const float* __restrict__ Wt   = (CFG==0)?d_W2t:(CFG==1)?d_W3bt:d_W4t;
    const float* __restrict__ Xin  = (CFG==0)?d_h :(CFG==1)?d_f   :d_h3;
    const float* __restrict__ bias = (CFG==0)?d_b2f:(CFG==1)?d_b3f:d_b4f;
    float*    Cout   = (CFG==0)?d_f:d_h3;          // unused for CFG2
    unsigned* keybuf = (CFG==0)?d_gkey:d_vkey;     // unused for CFG1

    const int tid = threadIdx.x;
    const int tm = tid >> 4;          // 0..15
    const int tn = tid & 15;          // 0..15
    const int j0 = blockIdx.x * 128;
    const int m0 = blockIdx.y * 128;

    __shared__ __align__(16) float As[8][128];
    __shared__ __align__(16) float Bs[8][128];
    __shared__ float red[16][128];

    float acc[8][8];
    #pragma unroll
    for (int i = 0; i < 8; i++)
        #pragma unroll
        for (int j = 0; j < 8; j++) acc[i][j] = 0.0f;

    const int lrow = tid >> 5;          // 0..7
    const int lcol = (tid & 31) * 4;    // 0..124

    for (int k0 = 0; k0 < K; k0 += 8) {
        float4 wa = *reinterpret_cast<const float4*>(&Wt[(size_t)(k0 + lrow) * M + m0 + lcol]);
        float4 xb = *reinterpret_cast<const float4*>(&Xin[(size_t)(k0 + lrow) * NPTS + j0 + lcol]);
        __syncthreads();
        *reinterpret_cast<float4*>(&As[lrow][lcol]) = wa;
        *reinterpret_cast<float4*>(&Bs[lrow][lcol]) = xb;
        __syncthreads();
        #pragma unroll
        for (int kk = 0; kk < 8; kk++) {
            float4 a0 = *reinterpret_cast<const float4*>(&As[kk][tm * 8]);
            float4 a1 = *reinterpret_cast<const float4*>(&As[kk][tm * 8 + 4]);
            float4 b0 = *reinterpret_cast<const float4*>(&Bs[kk][tn * 8]);
            float4 b1 = *reinterpret_cast<const float4*>(&Bs[kk][tn * 8 + 4]);
            float ar[8] = {a0.x,a0.y,a0.z,a0.w,a1.x,a1.y,a1.z,a1.w};
            float br[8] = {b0.x,b0.y,b0.z,b0.w,b1.x,b1.y,b1.z,b1.w};
            #pragma unroll
            for (int i = 0; i < 8; i++)
                #pragma unroll
                for (int j = 0; j < 8; j++)
                    acc[i][j] += ar[i] * br[j];
        }
    }

    // -------- epilogue --------
    const int jb = j0 + tn * 8;
    int sc[8];
    if (ADDU || SEGMAX) {
        #pragma unroll
        for (int j = 0; j < 8; j++) sc[j] = d_seg[jb + j];
    }
    #pragma unroll
    for (int i = 0; i < 8; i++) {
        const int mrow = m0 + tm * 8 + i;
        const float bb = bias[mrow];
        #pragma unroll
        for (int j = 0; j < 8; j++) {
            float val = acc[i][j] + bb;
            if (ADDU) val += d_u[mrow * BSEG + sc[j]];
            if (RELU) val = fmaxf(val, 0.0f);
            acc[i][j] = val;
        }
        if (WRITE) {
            float4 w0 = make_float4(acc[i][0], acc[i][1], acc[i][2], acc[i][3]);
            float4 w1 = make_float4(acc[i][4], acc[i][5], acc[i][6], acc[i][7]);
            *reinterpret_cast<float4*>(&Cout[(size_t)mrow * NPTS + jb])     = w0;
            *reinterpret_cast<float4*>(&Cout[(size_t)mrow * NPTS + jb + 4]) = w1;
        }
    }

    if (SEGMAX) {
        const int sl = d_seg[j0];
        const int sh = d_seg[j0 + 127];
        const int np = (sl == sh) ? 1 : 2;
        for (int pass = 0; pass < np; ++pass) {
            const int s = pass ? sh : sl;
            __syncthreads();
            #pragma unroll
            for (int i = 0; i < 8; i++) {
                float mx = -3.402823466e38f;
                #pragma unroll
                for (int j = 0; j < 8; j++)
                    if (sc[j] == s) mx = fmaxf(mx, acc[i][j]);
                red[tn][tm * 8 + i] = mx;
            }
            __syncthreads();
            if (tid < 128) {
                float mx = red[0][tid];
                #pragma unroll
                for (int t = 1; t < 16; t++) mx = fmaxf(mx, red[t][tid]);
                atomicMax(&keybuf[s * M + m0 + tid], f2key(mx));
            }
        }
    }
}

// ---------------- launch ----------------
extern "C" void kernel_launch(void* const* d_in, const int* in_sizes, int n_in,
                              void* d_out, int out_size) {
    const float* x    = (const float*)d_in[0];
    const int*   npts = (const int*  )d_in[1];
    const float *W1 = (const float*)d_in[2],  *b1 = (const float*)d_in[3],
                *g1 = (const float*)d_in[4],  *be1= (const float*)d_in[5],
                *m1 = (const float*)d_in[6],  *v1 = (const float*)d_in[7];
    const float *W2 = (const float*)d_in[8],  *b2 = (const float*)d_in[9],
                *g2 = (const float*)d_in[10], *be2= (const float*)d_in[11],
                *m2 = (const float*)d_in[12], *v2 = (const float*)d_in[13];
    const float *W3 = (const float*)d_in[14], *b3 = (const float*)d_in[15],
                *g3 = (const float*)d_in[16], *be3= (const float*)d_in[17],
                *m3 = (const float*)d_in[18], *v3 = (const float*)d_in[19];
    const float *W4 = (const float*)d_in[20], *b4 = (const float*)d_in[21],
                *g4 = (const float*)d_in[22], *be4= (const float*)d_in[23],
                *m4 = (const float*)d_in[24], *v4 = (const float*)d_in[25];

    init_keys_kernel<<<(BSEG * 1024 + 255) / 256, 256>>>();
    prep_kernel<1><<<32,  256>>>(W1, b1, g1, be1, m1, v1);
    prep_kernel<2><<<128, 256>>>(W2, b2, g2, be2, m2, v2);
    prep_kernel<3><<<512, 256>>>(W3, b3, g3, be3, m3, v3);
    prep_kernel<4><<<1024,256>>>(W4, b4, g4, be4, m4, v4);
    compute_offs_kernel<<<1, 32>>>(npts);
    fill_seg_kernel<<<NPTS / 256, 256>>>();
    k_h_kernel<<<(128 * NPTS) / 256, 256>>>(x);

    gemm_kernel<0><<<dim3(NPTS / 128, 2), 256>>>();   // f + partial g-max
    fin_g_kernel<<<16, 256>>>();
    k_u_kernel<<<32, 256>>>(W3, g3, v3);
    gemm_kernel<1><<<dim3(NPTS / 128, 4), 256>>>();   // h3
    gemm_kernel<2><<<dim3(NPTS / 128, 8), 256>>>();   // h4 + v-max
    fin_v_kernel<<<64, 256>>>((float*)d_out);
}

// round 2
// speedup vs baseline: 1.0517x; 1.0517x over previous
#include <cuda_runtime.h>
#include <cuda_bf16.h>
#include <cstdint>

#define NPTS 131072
#define BSEG 16
#define EPSF 1e-5f

// ---------------- scratch (__device__ globals: allocation-free) ----------------
__device__ float d_h  [128 * NPTS];   // relu(bn1(W1 x))
__device__ float d_f  [256 * NPTS];   // bn2(W2 h)
__device__ float d_h3 [512 * NPTS];   // relu(bn3(W3 xc))
__device__ float d_W1t[3   * 128];    // folded, transposed [k][c]
__device__ float d_b1f[128];
__device__ float d_W2t[128 * 256];
__device__ float d_b2f[256];
__device__ float d_W3bt[256 * 512];   // only cols 256..511 of W3 (f part)
__device__ float d_b3f[512];
__device__ float d_u  [512 * BSEG];   // W3a' @ g^T  (per-segment bias)
__device__ float d_W4t[512 * 1024];
__device__ float d_b4f[1024];
__device__ unsigned d_gkey[BSEG * 256];
__device__ float    d_gf  [BSEG * 256];
__device__ unsigned d_vkey[BSEG * 1024];
__device__ int d_seg [NPTS];
__device__ int d_offs[BSEG + 1];

// monotonic float<->uint keys for atomicMax-based float max
__device__ __forceinline__ unsigned f2key(float f) {
    unsigned u = __float_as_uint(f);
    return (u & 0x80000000u) ? ~u : (u | 0x80000000u);
}
__device__ __forceinline__ float key2f(unsigned k) {
    return (k & 0x80000000u) ? __uint_as_float(k & 0x7FFFFFFFu)
                             : __uint_as_float(~k);
}

// ---------------- small setup kernels ----------------
__global__ void init_keys_kernel() {
    int i = blockIdx.x * blockDim.x + threadIdx.x;
    if (i < BSEG * 256)  d_gkey[i] = 0u;
    if (i < BSEG * 1024) d_vkey[i] = 0u;
}

// fold BN into weights: Wt[k*C+c] = s[c]*W[c][KOFF+k], bf[c] = s*b + be - s*m
template<int L>
__global__ void prep_kernel(const float* __restrict__ W, const float* __restrict__ b,
                            const float* __restrict__ g, const float* __restrict__ be,
                            const float* __restrict__ m, const float* __restrict__ v) {
    constexpr int C    = (L==1)?128:(L==2)?256:(L==3)?512:1024;
    constexpr int KOUT = (L==1)?3  :(L==2)?128:(L==3)?256:512;
    constexpr int KSRC = (L==1)?3  :(L==2)?128:512;
    constexpr int KOFF = (L==3)?256:0;
    float* Wt = (L==1)?d_W1t:(L==2)?d_W2t:(L==3)?d_W3bt:d_W4t;
    float* bf = (L==1)?d_b1f:(L==2)?d_b2f:(L==3)?d_b3f:d_b4f;
    const int stride = gridDim.x * blockDim.x;
    const int t0 = blockIdx.x * blockDim.x + threadIdx.x;
    for (int i = t0; i < C; i += stride) {
        float s = g[i] * rsqrtf(v[i] + EPSF);
        bf[i] = s * b[i] + be[i] - s * m[i];
    }
    for (int idx = t0; idx < C * KOUT; idx += stride) {
        int k = idx / C, c = idx % C;
        float s = g[c] * rsqrtf(v[c] + EPSF);
        Wt[idx] = s * W[c * KSRC + KOFF + k];
    }
}

__global__ void compute_offs_kernel(const int* __restrict__ npts) {
    if (threadIdx.x == 0 && blockIdx.x == 0) {
        int a = 0;
        for (int s = 0; s < BSEG; s++) { d_offs[s] = a; a += npts[s]; }
        d_offs[BSEG] = a;
    }
}

__global__ void fill_seg_kernel() {
    int j = blockIdx.x * blockDim.x + threadIdx.x;
    if (j < NPTS) {
        int s = 0;
        #pragma unroll
        for (int t = 1; t < BSEG; t++) if (j >= d_offs[t]) s = t;
        d_seg[j] = s;
    }
}

// layer1: h = relu(W1' x + b1'), K=3 trivial
__global__ void k_h_kernel(const float* __restrict__ x) {
    int idx = blockIdx.x * blockDim.x + threadIdx.x;  // over 128*NPTS
    int c = idx / NPTS;
    int j = idx - c * NPTS;
    float val = d_b1f[c]
              + d_W1t[0 * 128 + c] * x[j]
              + d_W1t[1 * 128 + c] * x[NPTS + j]
              + d_W1t[2 * 128 + c] * x[2 * NPTS + j];
    d_h[idx] = fmaxf(val, 0.0f);
}

__global__ void fin_g_kernel() {
    int i = blockIdx.x * blockDim.x + threadIdx.x;
    if (i < BSEG * 256) d_gf[i] = key2f(d_gkey[i]);
}

// u[m][s] = s3[m] * sum_{r<256} W3[m][r] * g[s][r]
__global__ void k_u_kernel(const float* __restrict__ W3,
                           const float* __restrict__ g3,
                           const float* __restrict__ v3) {
    int idx = blockIdx.x * blockDim.x + threadIdx.x;  // 512*16
    if (idx >= 512 * BSEG) return;
    int m = idx >> 4, s = idx & 15;
    float sc = g3[m] * rsqrtf(v3[m] + EPSF);
    float acc = 0.0f;
    for (int r = 0; r < 256; r++)
        acc += W3[m * 512 + r] * d_gf[s * 256 + r];
    d_u[m * BSEG + s] = sc * acc;
}

__global__ void fin_v_kernel(float* __restrict__ out) {
    int i = blockIdx.x * blockDim.x + threadIdx.x;
    if (i < BSEG * 1024) out[i] = key2f(d_vkey[i]);
}

// ---------------- the SGEMM workhorse ----------------
// C[M][NPTS] = Wt[K][M]^T applied to Xin[K][NPTS], + bias, (+u[m][seg]), (relu),
// (write C), (segment-max -> keybuf).
// Block tile 128x128, 256 threads, 8x8 per thread, K-chunk 8.
// CFG0: f  = W2t @ h   (M=256,K=128, write + segmax->gkey)
// CFG1: h3 = relu(W3bt @ f + u[seg]) (M=512,K=256, write)
// CFG2: v  = segmax(W4t @ h3)        (M=1024,K=512, segmax->vkey only)
template<int CFG>
__global__ void __launch_bounds__(256)
gemm_kernel() {
    constexpr int  M      = (CFG==0)?256:(CFG==1)?512:1024;
    constexpr int  K      = (CFG==0)?128:(CFG==1)?256:512;
    constexpr bool RELU   = (CFG==1);
    constexpr bool ADDU   = (CFG==1);
    constexpr bool WRITE  = (CFG!=2);
    constexpr bool SEGMAX = (CFG!=1);

    const float* __restrict__ Wt   = (CFG==0)?d_W2t:(CFG==1)?d_W3bt:d_W4t;
    const float* __restrict__ Xin  = (CFG==0)?d_h :(CFG==1)?d_f   :d_h3;
    const float* __restrict__ bias = (CFG==0)?d_b2f:(CFG==1)?d_b3f:d_b4f;
    float*    Cout   = (CFG==0)?d_f:d_h3;          // unused for CFG2
    unsigned* keybuf = (CFG==0)?d_gkey:d_vkey;     // unused for CFG1

    const int tid = threadIdx.x;
    const int tm = tid >> 4;          // 0..15
    const int tn = tid & 15;          // 0..15
    const int j0 = blockIdx.x * 128;
    const int m0 = blockIdx.y * 128;

    __shared__ __align__(16) float As[8][128];
    __shared__ __align__(16) float Bs[8][128];
    __shared__ float red[16][128];

    float acc[8][8];
    #pragma unroll
    for (int i = 0; i < 8; i++)
        #pragma unroll
        for (int j = 0; j < 8; j++) acc[i][j] = 0.0f;

    const int lrow = tid >> 5;          // 0..7
    const int lcol = (tid & 31) * 4;    // 0..124

    for (int k0 = 0; k0 < K; k0 += 8) {
        float4 wa = *reinterpret_cast<const float4*>(&Wt[(size_t)(k0 + lrow) * M + m0 + lcol]);
        float4 xb = *reinterpret_cast<const float4*>(&Xin[(size_t)(k0 + lrow) * NPTS + j0 + lcol]);
        __syncthreads();
        *reinterpret_cast<float4*>(&As[lrow][lcol]) = wa;
        *reinterpret_cast<float4*>(&Bs[lrow][lcol]) = xb;
        __syncthreads();
        #pragma unroll
        for (int kk = 0; kk < 8; kk++) {
            float4 a0 = *reinterpret_cast<const float4*>(&As[kk][tm * 8]);
            float4 a1 = *reinterpret_cast<const float4*>(&As[kk][tm * 8 + 4]);
            float4 b0 = *reinterpret_cast<const float4*>(&Bs[kk][tn * 8]);
            float4 b1 = *reinterpret_cast<const float4*>(&Bs[kk][tn * 8 + 4]);
            float ar[8] = {a0.x,a0.y,a0.z,a0.w,a1.x,a1.y,a1.z,a1.w};
            float br[8] = {b0.x,b0.y,b0.z,b0.w,b1.x,b1.y,b1.z,b1.w};
            #pragma unroll
            for (int i = 0; i < 8; i++)
                #pragma unroll
                for (int j = 0; j < 8; j++)
                    acc[i][j] += ar[i] * br[j];
        }
    }

    // -------- epilogue --------
    const int jb = j0 + tn * 8;
    int sc[8];
    if (ADDU || SEGMAX) {
        #pragma unroll
        for (int j = 0; j < 8; j++) sc[j] = d_seg[jb + j];
    }
    #pragma unroll
    for (int i = 0; i < 8; i++) {
        const int mrow = m0 + tm * 8 + i;
        const float bb = bias[mrow];
        #pragma unroll
        for (int j = 0; j < 8; j++) {
            float val = acc[i][j] + bb;
            if (ADDU) val += d_u[mrow * BSEG + sc[j]];
            if (RELU) val = fmaxf(val, 0.0f);
            acc[i][j] = val;
        }
        if (WRITE) {
            float4 w0 = make_float4(acc[i][0], acc[i][1], acc[i][2], acc[i][3]);
            float4 w1 = make_float4(acc[i][4], acc[i][5], acc[i][6], acc[i][7]);
            *reinterpret_cast<float4*>(&Cout[(size_t)mrow * NPTS + jb])     = w0;
            *reinterpret_cast<float4*>(&Cout[(size_t)mrow * NPTS + jb + 4]) = w1;
        }
    }

    if (SEGMAX) {
        const int sl = d_seg[j0];
        const int sh = d_seg[j0 + 127];
        const int np = (sl == sh) ? 1 : 2;
        for (int pass = 0; pass < np; ++pass) {
            const int s = pass ? sh : sl;
            __syncthreads();
            #pragma unroll
            for (int i = 0; i < 8; i++) {
                float mx = -3.402823466e38f;
                #pragma unroll
                for (int j = 0; j < 8; j++)
                    if (sc[j] == s) mx = fmaxf(mx, acc[i][j]);
                red[tn][tm * 8 + i] = mx;
            }
            __syncthreads();
            if (tid < 128) {
                float mx = red[0][tid];
                #pragma unroll
                for (int t = 1; t < 16; t++) mx = fmaxf(mx, red[t][tid]);
                atomicMax(&keybuf[s * M + m0 + tid], f2key(mx));
            }
        }
    }
}

// ---------------- launch ----------------
extern "C" void kernel_launch(void* const* d_in, const int* in_sizes, int n_in,
                              void* d_out, int out_size) {
    const float* x    = (const float*)d_in[0];
    const int*   npts = (const int*  )d_in[1];
    const float *W1 = (const float*)d_in[2],  *b1 = (const float*)d_in[3],
                *g1 = (const float*)d_in[4],  *be1= (const float*)d_in[5],
                *m1 = (const float*)d_in[6],  *v1 = (const float*)d_in[7];
    const float *W2 = (const float*)d_in[8],  *b2 = (const float*)d_in[9],
                *g2 = (const float*)d_in[10], *be2= (const float*)d_in[11],
                *m2 = (const float*)d_in[12], *v2 = (const float*)d_in[13];
    const float *W3 = (const float*)d_in[14], *b3 = (const float*)d_in[15],
                *g3 = (const float*)d_in[16], *be3= (const float*)d_in[17],
                *m3 = (const float*)d_in[18], *v3 = (const float*)d_in[19];
    const float *W4 = (const float*)d_in[20], *b4 = (const float*)d_in[21],
                *g4 = (const float*)d_in[22], *be4= (const float*)d_in[23],
                *m4 = (const float*)d_in[24], *v4 = (const float*)d_in[25];

    init_keys_kernel<<<(BSEG * 1024 + 255) / 256, 256>>>();
    prep_kernel<1><<<32,  256>>>(W1, b1, g1, be1, m1, v1);
    prep_kernel<2><<<128, 256>>>(W2, b2, g2, be2, m2, v2);
    prep_kernel<3><<<512, 256>>>(W3, b3, g3, be3, m3, v3);
    prep_kernel<4><<<1024,256>>>(W4, b4, g4, be4, m4, v4);
    compute_offs_kernel<<<1, 32>>>(npts);
    fill_seg_kernel<<<NPTS / 256, 256>>>();
    k_h_kernel<<<(128 * NPTS) / 256, 256>>>(x);

    gemm_kernel<0><<<dim3(NPTS / 128, 2), 256>>>();   // f + partial g-max
    fin_g_kernel<<<16, 256>>>();
    k_u_kernel<<<32, 256>>>(W3, g3, v3);
    gemm_kernel<1><<<dim3(NPTS / 128, 4), 256>>>();   // h3
    gemm_kernel<2><<<dim3(NPTS / 128, 8), 256>>>();   // h4 + v-max
    fin_v_kernel<<<64, 256>>>((float*)d_out);
}

// round 3
// speedup vs baseline: 1.0521x; 1.0004x over previous
#include <cuda_runtime.h>
#include <cuda_bf16.h>
#include <cstdint>

#define NPTS 131072
#define BSEG 16
#define EPSF 1e-5f

// ---------------- scratch (__device__ globals: allocation-free) ----------------
__device__ float d_h  [128 * NPTS];   // relu(bn1(W1 x))
__device__ float d_f  [256 * NPTS];   // bn2(W2 h)
__device__ float d_h3 [512 * NPTS];   // relu(bn3(W3 xc))
__device__ float d_W1t[3   * 128];    // folded, transposed [k][c]
__device__ float d_b1f[128];
__device__ float d_W2t[128 * 256];
__device__ float d_b2f[256];
__device__ float d_W3bt[256 * 512];   // only cols 256..511 of W3 (f part)
__device__ float d_b3f[512];
__device__ float d_u  [512 * BSEG];   // W3a' @ g^T  (per-segment bias)
__device__ float d_W4t[512 * 1024];
__device__ float d_b4f[1024];
__device__ unsigned d_gkey[BSEG * 256];
__device__ float    d_gf  [BSEG * 256];
__device__ unsigned d_vkey[BSEG * 1024];
__device__ int d_seg [NPTS];
__device__ int d_offs[BSEG + 1];

// monotonic float<->uint keys for atomicMax-based float max
__device__ __forceinline__ unsigned f2key(float f) {
    unsigned u = __float_as_uint(f);
    return (u & 0x80000000u) ? ~u : (u | 0x80000000u);
}
__device__ __forceinline__ float key2f(unsigned k) {
    return (k & 0x80000000u) ? __uint_as_float(k & 0x7FFFFFFFu)
                             : __uint_as_float(~k);
}

// ---------------- small setup kernels ----------------
__global__ void init_keys_kernel() {
    int i = blockIdx.x * blockDim.x + threadIdx.x;
    if (i < BSEG * 256)  d_gkey[i] = 0u;
    if (i < BSEG * 1024) d_vkey[i] = 0u;
}

// fold BN into weights: Wt[k*C+c] = s[c]*W[c][KOFF+k], bf[c] = s*b + be - s*m
template<int L>
__global__ void prep_kernel(const float* __restrict__ W, const float* __restrict__ b,
                            const float* __restrict__ g, const float* __restrict__ be,
                            const float* __restrict__ m, const float* __restrict__ v) {
    constexpr int C    = (L==1)?128:(L==2)?256:(L==3)?512:1024;
    constexpr int KOUT = (L==1)?3  :(L==2)?128:(L==3)?256:512;
    constexpr int KSRC = (L==1)?3  :(L==2)?128:512;
    constexpr int KOFF = (L==3)?256:0;
    float* Wt = (L==1)?d_W1t:(L==2)?d_W2t:(L==3)?d_W3bt:d_W4t;
    float* bf = (L==1)?d_b1f:(L==2)?d_b2f:(L==3)?d_b3f:d_b4f;
    const int stride = gridDim.x * blockDim.x;
    const int t0 = blockIdx.x * blockDim.x + threadIdx.x;
    for (int i = t0; i < C; i += stride) {
        float s = g[i] * rsqrtf(v[i] + EPSF);
        bf[i] = s * b[i] + be[i] - s * m[i];
    }
    for (int idx = t0; idx < C * KOUT; idx += stride) {
        int k = idx / C, c = idx % C;
        float s = g[c] * rsqrtf(v[c] + EPSF);
        Wt[idx] = s * W[c * KSRC + KOFF + k];
    }
}

__global__ void compute_offs_kernel(const int* __restrict__ npts) {
    if (threadIdx.x == 0 && blockIdx.x == 0) {
        int a = 0;
        for (int s = 0; s < BSEG; s++) { d_offs[s] = a; a += npts[s]; }
        d_offs[BSEG] = a;
    }
}

__global__ void fill_seg_kernel() {
    int j = blockIdx.x * blockDim.x + threadIdx.x;
    if (j < NPTS) {
        int s = 0;
        #pragma unroll
        for (int t = 1; t < BSEG; t++) if (j >= d_offs[t]) s = t;
        d_seg[j] = s;
    }
}

// layer1: h = relu(W1' x + b1'), K=3 trivial
__global__ void k_h_kernel(const float* __restrict__ x) {
    int idx = blockIdx.x * blockDim.x + threadIdx.x;  // over 128*NPTS
    int c = idx / NPTS;
    int j = idx - c * NPTS;
    float val = d_b1f[c]
              + d_W1t[0 * 128 + c] * x[j]
              + d_W1t[1 * 128 + c] * x[NPTS + j]
              + d_W1t[2 * 128 + c] * x[2 * NPTS + j];
    d_h[idx] = fmaxf(val, 0.0f);
}

__global__ void fin_g_kernel() {
    int i = blockIdx.x * blockDim.x + threadIdx.x;
    if (i < BSEG * 256) d_gf[i] = key2f(d_gkey[i]);
}

// u[m][s] = s3[m] * sum_{r<256} W3[m][r] * g[s][r]
__global__ void k_u_kernel(const float* __restrict__ W3,
                           const float* __restrict__ g3,
                           const float* __restrict__ v3) {
    int idx = blockIdx.x * blockDim.x + threadIdx.x;  // 512*16
    if (idx >= 512 * BSEG) return;
    int m = idx >> 4, s = idx & 15;
    float sc = g3[m] * rsqrtf(v3[m] + EPSF);
    float acc = 0.0f;
    for (int r = 0; r < 256; r++)
        acc += W3[m * 512 + r] * d_gf[s * 256 + r];
    d_u[m * BSEG + s] = sc * acc;
}

__global__ void fin_v_kernel(float* __restrict__ out) {
    int i = blockIdx.x * blockDim.x + threadIdx.x;
    if (i < BSEG * 1024) out[i] = key2f(d_vkey[i]);
}

// ---------------- the SGEMM workhorse ----------------
// C[M][NPTS] = Wt[K][M]^T applied to Xin[K][NPTS], + bias, (+u[m][seg]), (relu),
// (write C), (segment-max -> keybuf).
// Block tile 128x128, 256 threads, 8x8 per thread, K-chunk 8.
// CFG0: f  = W2t @ h   (M=256,K=128, write + segmax->gkey)
// CFG1: h3 = relu(W3bt @ f + u[seg]) (M=512,K=256, write)
// CFG2: v  = segmax(W4t @ h3)        (M=1024,K=512, segmax->vkey only)
template<int CFG>
__global__ void __launch_bounds__(256)
gemm_kernel() {
    constexpr int  M      = (CFG==0)?256:(CFG==1)?512:1024;
    constexpr int  K      = (CFG==0)?128:(CFG==1)?256:512;
    constexpr bool RELU   = (CFG==1);
    constexpr bool ADDU   = (CFG==1);
    constexpr bool WRITE  = (CFG!=2);
    constexpr bool SEGMAX = (CFG!=1);

    const float* __restrict__ Wt   = (CFG==0)?d_W2t:(CFG==1)?d_W3bt:d_W4t;
    const float* __restrict__ Xin  = (CFG==0)?d_h :(CFG==1)?d_f   :d_h3;
    const float* __restrict__ bias = (CFG==0)?d_b2f:(CFG==1)?d_b3f:d_b4f;
    float*    Cout   = (CFG==0)?d_f:d_h3;          // unused for CFG2
    unsigned* keybuf = (CFG==0)?d_gkey:d_vkey;     // unused for CFG1

    const int tid = threadIdx.x;
    const int tm = tid >> 4;          // 0..15
    const int tn = tid & 15;          // 0..15
    const int j0 = blockIdx.x * 128;
    const int m0 = blockIdx.y * 128;

    __shared__ __align__(16) float As[8][128];
    __shared__ __align__(16) float Bs[8][128];
    __shared__ float red[16][128];

    float acc[8][8];
    #pragma unroll
    for (int i = 0; i < 8; i++)
        #pragma unroll
        for (int j = 0; j < 8; j++) acc[i][j] = 0.0f;

    const int lrow = tid >> 5;          // 0..7
    const int lcol = (tid & 31) * 4;    // 0..124

    for (int k0 = 0; k0 < K; k0 += 8) {
        float4 wa = *reinterpret_cast<const float4*>(&Wt[(size_t)(k0 + lrow) * M + m0 + lcol]);
        float4 xb = *reinterpret_cast<const float4*>(&Xin[(size_t)(k0 + lrow) * NPTS + j0 + lcol]);
        __syncthreads();
        *reinterpret_cast<float4*>(&As[lrow][lcol]) = wa;
        *reinterpret_cast<float4*>(&Bs[lrow][lcol]) = xb;
        __syncthreads();
        #pragma unroll
        for (int kk = 0; kk < 8; kk++) {
            float4 a0 = *reinterpret_cast<const float4*>(&As[kk][tm * 8]);
            float4 a1 = *reinterpret_cast<const float4*>(&As[kk][tm * 8 + 4]);
            float4 b0 = *reinterpret_cast<const float4*>(&Bs[kk][tn * 8]);
            float4 b1 = *reinterpret_cast<const float4*>(&Bs[kk][tn * 8 + 4]);
            float ar[8] = {a0.x,a0.y,a0.z,a0.w,a1.x,a1.y,a1.z,a1.w};
            float br[8] = {b0.x,b0.y,b0.z,b0.w,b1.x,b1.y,b1.z,b1.w};
            #pragma unroll
            for (int i = 0; i < 8; i++)
                #pragma unroll
                for (int j = 0; j < 8; j++)
                    acc[i][j] += ar[i] * br[j];
        }
    }

    // -------- epilogue --------
    const int jb = j0 + tn * 8;
    int sc[8];
    if (ADDU || SEGMAX) {
        #pragma unroll
        for (int j = 0; j < 8; j++) sc[j] = d_seg[jb + j];
    }
    #pragma unroll
    for (int i = 0; i < 8; i++) {
        const int mrow = m0 + tm * 8 + i;
        const float bb = bias[mrow];
        #pragma unroll
        for (int j = 0; j < 8; j++) {
            float val = acc[i][j] + bb;
            if (ADDU) val += d_u[mrow * BSEG + sc[j]];
            if (RELU) val = fmaxf(val, 0.0f);
            acc[i][j] = val;
        }
        if (WRITE) {
            float4 w0 = make_float4(acc[i][0], acc[i][1], acc[i][2], acc[i][3]);
            float4 w1 = make_float4(acc[i][4], acc[i][5], acc[i][6], acc[i][7]);
            *reinterpret_cast<float4*>(&Cout[(size_t)mrow * NPTS + jb])     = w0;
            *reinterpret_cast<float4*>(&Cout[(size_t)mrow * NPTS + jb + 4]) = w1;
        }
    }

    if (SEGMAX) {
        const int sl = d_seg[j0];
        const int sh = d_seg[j0 + 127];
        const int np = (sl == sh) ? 1 : 2;
        for (int pass = 0; pass < np; ++pass) {
            const int s = pass ? sh : sl;
            __syncthreads();
            #pragma unroll
            for (int i = 0; i < 8; i++) {
                float mx = -3.402823466e38f;
                #pragma unroll
                for (int j = 0; j < 8; j++)
                    if (sc[j] == s) mx = fmaxf(mx, acc[i][j]);
                red[tn][tm * 8 + i] = mx;
            }
            __syncthreads();
            if (tid < 128) {
                float mx = red[0][tid];
                #pragma unroll
                for (int t = 1; t < 16; t++) mx = fmaxf(mx, red[t][tid]);
                atomicMax(&keybuf[s * M + m0 + tid], f2key(mx));
            }
        }
    }
}

// ---------------- launch ----------------
extern "C" void kernel_launch(void* const* d_in, const int* in_sizes, int n_in,
                              void* d_out, int out_size) {
    const float* x    = (const float*)d_in[0];
    const int*   npts = (const int*  )d_in[1];
    const float *W1 = (const float*)d_in[2],  *b1 = (const float*)d_in[3],
                *g1 = (const float*)d_in[4],  *be1= (const float*)d_in[5],
                *m1 = (const float*)d_in[6],  *v1 = (const float*)d_in[7];
    const float *W2 = (const float*)d_in[8],  *b2 = (const float*)d_in[9],
                *g2 = (const float*)d_in[10], *be2= (const float*)d_in[11],
                *m2 = (const float*)d_in[12], *v2 = (const float*)d_in[13];
    const float *W3 = (const float*)d_in[14], *b3 = (const float*)d_in[15],
                *g3 = (const float*)d_in[16], *be3= (const float*)d_in[17],
                *m3 = (const float*)d_in[18], *v3 = (const float*)d_in[19];
    const float *W4 = (const float*)d_in[20], *b4 = (const float*)d_in[21],
                *g4 = (const float*)d_in[22], *be4= (const float*)d_in[23],
                *m4 = (const float*)d_in[24], *v4 = (const float*)d_in[25];

    init_keys_kernel<<<(BSEG * 1024 + 255) / 256, 256>>>();
    prep_kernel<1><<<32,  256>>>(W1, b1, g1, be1, m1, v1);
    prep_kernel<2><<<128, 256>>>(W2, b2, g2, be2, m2, v2);
    prep_kernel<3><<<512, 256>>>(W3, b3, g3, be3, m3, v3);
    prep_kernel<4><<<1024,256>>>(W4, b4, g4, be4, m4, v4);
    compute_offs_kernel<<<1, 32>>>(npts);
    fill_seg_kernel<<<NPTS / 256, 256>>>();
    k_h_kernel<<<(128 * NPTS) / 256, 256>>>(x);

    gemm_kernel<0><<<dim3(NPTS / 128, 2), 256>>>();   // f + partial g-max
    fin_g_kernel<<<16, 256>>>();
    k_u_kernel<<<32, 256>>>(W3, g3, v3);
    gemm_kernel<1><<<dim3(NPTS / 128, 4), 256>>>();   // h3
    gemm_kernel<2><<<dim3(NPTS / 128, 8), 256>>>();   // h4 + v-max
    fin_v_kernel<<<64, 256>>>((float*)d_out);
}

// round 4
// speedup vs baseline: 1.3298x; 1.2640x over previous
#include <cuda_runtime.h>
#include <cstdint>

#define NPTS 131072
#define BSEG 16
#define EPSF 1e-5f

// ---------------- scratch (__device__ globals: allocation-free) ----------------
__device__ float d_f  [256 * NPTS];   // bn2(W2 h)
__device__ float d_h3 [512 * NPTS];   // relu(bn3(W3 xc))
__device__ float d_W1t[3   * 128];    // folded, transposed [k][c]
__device__ float d_b1f[128];
__device__ float d_W2t[128 * 256];
__device__ float d_b2f[256];
__device__ float d_W3bt[256 * 512];   // only cols 256..511 of W3 (f part)
__device__ float d_b3f[512];
__device__ float d_u  [512 * BSEG];   // W3a' @ g^T  (per-segment bias)
__device__ float d_W4t[512 * 1024];
__device__ float d_b4f[1024];
__device__ unsigned d_gkey[BSEG * 256];
__device__ float    d_gf  [BSEG * 256];
__device__ unsigned d_vkey[BSEG * 1024];
__device__ int d_seg [NPTS];

// monotonic float<->uint keys for atomicMax-based float max
__device__ __forceinline__ unsigned f2key(float f) {
    unsigned u = __float_as_uint(f);
    return (u & 0x80000000u) ? ~u : (u | 0x80000000u);
}
__device__ __forceinline__ float key2f(unsigned k) {
    return (k & 0x80000000u) ? __uint_as_float(k & 0x7FFFFFFFu)
                             : __uint_as_float(~k);
}

// ---------------- packed f32x2 helpers (FFMA2 path) ----------------
__device__ __forceinline__ unsigned long long pack2(float lo, float hi) {
    unsigned long long r;
    asm("mov.b64 %0, {%1, %2};" : "=l"(r) : "f"(lo), "f"(hi));
    return r;
}
__device__ __forceinline__ void unpack2(unsigned long long v, float& lo, float& hi) {
    asm("mov.b64 {%0, %1}, %2;" : "=f"(lo), "=f"(hi) : "l"(v));
}
__device__ __forceinline__ void ffma2(unsigned long long& c,
                                      unsigned long long a, unsigned long long b) {
    asm("fma.rn.f32x2 %0, %1, %2, %0;" : "+l"(c) : "l"(a), "l"(b));
}

// ---------------- single merged setup kernel ----------------
__device__ __forceinline__ void fold_one(int t0, int stride,
                                         const float* __restrict__ W, const float* __restrict__ b,
                                         const float* __restrict__ g, const float* __restrict__ be,
                                         const float* __restrict__ m, const float* __restrict__ v,
                                         float* Wt, float* bf,
                                         int C, int KOUT, int KSRC, int KOFF) {
    for (int i = t0; i < C; i += stride) {
        float s = g[i] * rsqrtf(v[i] + EPSF);
        bf[i] = s * b[i] + be[i] - s * m[i];
    }
    for (int idx = t0; idx < C * KOUT; idx += stride) {
        int k = idx / C, c = idx % C;
        float s = g[c] * rsqrtf(v[c] + EPSF);
        Wt[idx] = s * W[c * KSRC + KOFF + k];
    }
}

__global__ void setup_kernel(const int* __restrict__ npts,
    const float* W1, const float* b1, const float* g1, const float* be1, const float* m1, const float* v1,
    const float* W2, const float* b2, const float* g2, const float* be2, const float* m2, const float* v2,
    const float* W3, const float* b3, const float* g3, const float* be3, const float* m3, const float* v3,
    const float* W4, const float* b4, const float* g4, const float* be4, const float* m4, const float* v4) {
    const int stride = gridDim.x * blockDim.x;
    const int t0 = blockIdx.x * blockDim.x + threadIdx.x;

    fold_one(t0, stride, W1, b1, g1, be1, m1, v1, d_W1t,  d_b1f, 128,  3,   3,   0);
    fold_one(t0, stride, W2, b2, g2, be2, m2, v2, d_W2t,  d_b2f, 256,  128, 128, 0);
    fold_one(t0, stride, W3, b3, g3, be3, m3, v3, d_W3bt, d_b3f, 512,  256, 512, 256);
    fold_one(t0, stride, W4, b4, g4, be4, m4, v4, d_W4t,  d_b4f, 1024, 512, 512, 0);

    // segment ids from npts (each thread computes its own cumsum — 16 ints, L2-hot)
    int cum[BSEG];
    {
        int a = 0;
        #pragma unroll
        for (int t = 0; t < BSEG; t++) { a += __ldg(&npts[t]); cum[t] = a; }
    }
    for (int j = t0; j < NPTS; j += stride) {
        int s = 0;
        #pragma unroll
        for (int t = 0; t < BSEG - 1; t++) s += (j >= cum[t]);
        d_seg[j] = s;
    }

    // zero atomic-max key buffers
    for (int i = t0; i < BSEG * 1024; i += stride) d_vkey[i] = 0u;
    for (int i = t0; i < BSEG * 256;  i += stride) d_gkey[i] = 0u;
}

__global__ void fin_g_kernel() {
    int i = blockIdx.x * blockDim.x + threadIdx.x;
    if (i < BSEG * 256) d_gf[i] = key2f(d_gkey[i]);
}

// u[m][s] = s3[m] * sum_{r<256} W3[m][r] * g[s][r]
__global__ void k_u_kernel(const float* __restrict__ W3,
                           const float* __restrict__ g3,
                           const float* __restrict__ v3) {
    int idx = blockIdx.x * blockDim.x + threadIdx.x;  // 512*16
    if (idx >= 512 * BSEG) return;
    int m = idx >> 4, s = idx & 15;
    float sc = g3[m] * rsqrtf(v3[m] + EPSF);
    float acc = 0.0f;
    for (int r = 0; r < 256; r++)
        acc += W3[m * 512 + r] * d_gf[s * 256 + r];
    d_u[m * BSEG + s] = sc * acc;
}

__global__ void fin_v_kernel(float* __restrict__ out) {
    int i = blockIdx.x * blockDim.x + threadIdx.x;
    if (i < BSEG * 1024) out[i] = key2f(d_vkey[i]);
}

// ---------------- the SGEMM workhorse (FFMA2 + double-buffered smem) ----------------
// Block tile 128x128, 256 threads, 8x8 per thread (stored as 4x8 f32x2 pairs along M).
// CFG0: f  = W2t @ relu(bn1(W1 x))  [layer1 fused into B-tile production], segmax->gkey
// CFG1: h3 = relu(W3bt @ f + u[seg])
// CFG2: v  = segmax(W4t @ h3)
template<int CFG>
__global__ void __launch_bounds__(256, 2)
gemm_kernel(const float* __restrict__ xg) {
    constexpr int  M      = (CFG==0)?256:(CFG==1)?512:1024;
    constexpr int  K      = (CFG==0)?128:(CFG==1)?256:512;
    constexpr bool RELU   = (CFG==1);
    constexpr bool ADDU   = (CFG==1);
    constexpr bool WRITE  = (CFG!=2);
    constexpr bool SEGMAX = (CFG!=1);
    constexpr bool FUSE1  = (CFG==0);

    const float* __restrict__ Wt   = (CFG==0)?d_W2t:(CFG==1)?d_W3bt:d_W4t;
    const float* __restrict__ Xin  = (CFG==1)?d_f:d_h3;     // unused for CFG0
    const float* __restrict__ bias = (CFG==0)?d_b2f:(CFG==1)?d_b3f:d_b4f;
    float*    Cout   = (CFG==0)?d_f:d_h3;          // unused for CFG2
    unsigned* keybuf = (CFG==0)?d_gkey:d_vkey;     // unused for CFG1

    const int tid = threadIdx.x;
    const int tm = tid >> 4;          // 0..15
    const int tn = tid & 15;          // 0..15
    const int j0 = blockIdx.x * 128;
    const int m0 = blockIdx.y * 128;
    const int lrow = tid >> 5;          // 0..7
    const int lcol = (tid & 31) * 4;    // 0..124

    __shared__ __align__(16) float As[2][8][128];
    __shared__ __align__(16) float Bs[2][8][128];
    __shared__ float red[16][128];
    __shared__ float xs[3][128];

    unsigned long long acc2[4][8];
    #pragma unroll
    for (int ii = 0; ii < 4; ii++)
        #pragma unroll
        for (int j = 0; j < 8; j++) acc2[ii][j] = 0ull;

    if (FUSE1) {
        for (int idx = tid; idx < 3 * 128; idx += 256)
            xs[idx >> 7][idx & 127] = xg[(size_t)(idx >> 7) * NPTS + j0 + (idx & 127)];
        __syncthreads();
    }

    // compute one fused layer-1 B value row kr, cols lcol..lcol+3
    auto fuseB = [&](int kr) -> float4 {
        float w0 = d_W1t[kr], w1 = d_W1t[128 + kr], w2 = d_W1t[256 + kr], bb = d_b1f[kr];
        float4 r;
        r.x = fmaxf(bb + w0 * xs[0][lcol]     + w1 * xs[1][lcol]     + w2 * xs[2][lcol],     0.0f);
        r.y = fmaxf(bb + w0 * xs[0][lcol + 1] + w1 * xs[1][lcol + 1] + w2 * xs[2][lcol + 1], 0.0f);
        r.z = fmaxf(bb + w0 * xs[0][lcol + 2] + w1 * xs[1][lcol + 2] + w2 * xs[2][lcol + 2], 0.0f);
        r.w = fmaxf(bb + w0 * xs[0][lcol + 3] + w1 * xs[1][lcol + 3] + w2 * xs[2][lcol + 3], 0.0f);
        return r;
    };

    // prologue: stage chunk 0
    {
        float4 wa = *reinterpret_cast<const float4*>(&Wt[(size_t)lrow * M + m0 + lcol]);
        float4 xb;
        if (FUSE1) xb = fuseB(lrow);
        else       xb = *reinterpret_cast<const float4*>(&Xin[(size_t)lrow * NPTS + j0 + lcol]);
        *reinterpret_cast<float4*>(&As[0][lrow][lcol]) = wa;
        *reinterpret_cast<float4*>(&Bs[0][lrow][lcol]) = xb;
    }
    __syncthreads();

    int buf = 0;
    #pragma unroll 2
    for (int k0 = 0; k0 < K; k0 += 8) {
        const bool next = (k0 + 8 < K);
        float4 nwa, nxb;
        if (next) {
            nwa = *reinterpret_cast<const float4*>(&Wt[(size_t)(k0 + 8 + lrow) * M + m0 + lcol]);
            if (FUSE1) nxb = fuseB(k0 + 8 + lrow);
            else       nxb = *reinterpret_cast<const float4*>(&Xin[(size_t)(k0 + 8 + lrow) * NPTS + j0 + lcol]);
        }
        // compute on current buffer: 32 FFMA2 per kk (2 flops each)
        #pragma unroll
        for (int kk = 0; kk < 8; kk++) {
            const unsigned long long* ap =
                reinterpret_cast<const unsigned long long*>(&As[buf][kk][tm * 8]);
            unsigned long long a20 = ap[0], a21 = ap[1], a22 = ap[2], a23 = ap[3];
            float4 b0 = *reinterpret_cast<const float4*>(&Bs[buf][kk][tn * 8]);
            float4 b1 = *reinterpret_cast<const float4*>(&Bs[buf][kk][tn * 8 + 4]);
            float br[8] = {b0.x, b0.y, b0.z, b0.w, b1.x, b1.y, b1.z, b1.w};
            #pragma unroll
            for (int j = 0; j < 8; j++) {
                unsigned long long bd = pack2(br[j], br[j]);
                ffma2(acc2[0][j], a20, bd);
                ffma2(acc2[1][j], a21, bd);
                ffma2(acc2[2][j], a22, bd);
                ffma2(acc2[3][j], a23, bd);
            }
        }
        if (next) {
            __syncthreads();
            *reinterpret_cast<float4*>(&As[buf ^ 1][lrow][lcol]) = nwa;
            *reinterpret_cast<float4*>(&Bs[buf ^ 1][lrow][lcol]) = nxb;
            __syncthreads();
            buf ^= 1;
        }
    }

    // unpack pairs (packed along M: lo -> row tm*8+2ii, hi -> row +1)
    float accf[8][8];
    #pragma unroll
    for (int ii = 0; ii < 4; ii++)
        #pragma unroll
        for (int j = 0; j < 8; j++)
            unpack2(acc2[ii][j], accf[2 * ii][j], accf[2 * ii + 1][j]);

    // -------- epilogue --------
    const int jb = j0 + tn * 8;
    int sc[8];
    if (ADDU || SEGMAX) {
        #pragma unroll
        for (int j = 0; j < 8; j++) sc[j] = d_seg[jb + j];
    }
    #pragma unroll
    for (int i = 0; i < 8; i++) {
        const int mrow = m0 + tm * 8 + i;
        const float bb = bias[mrow];
        #pragma unroll
        for (int j = 0; j < 8; j++) {
            float val = accf[i][j] + bb;
            if (ADDU) val += d_u[mrow * BSEG + sc[j]];
            if (RELU) val = fmaxf(val, 0.0f);
            accf[i][j] = val;
        }
        if (WRITE) {
            float4 w0 = make_float4(accf[i][0], accf[i][1], accf[i][2], accf[i][3]);
            float4 w1 = make_float4(accf[i][4], accf[i][5], accf[i][6], accf[i][7]);
            *reinterpret_cast<float4*>(&Cout[(size_t)mrow * NPTS + jb])     = w0;
            *reinterpret_cast<float4*>(&Cout[(size_t)mrow * NPTS + jb + 4]) = w1;
        }
    }

    if (SEGMAX) {
        const int sl = d_seg[j0];
        const int sh = d_seg[j0 + 127];
        const int np = (sl == sh) ? 1 : 2;
        for (int pass = 0; pass < np; ++pass) {
            const int s = pass ? sh : sl;
            __syncthreads();
            #pragma unroll
            for (int i = 0; i < 8; i++) {
                float mx = -3.402823466e38f;
                #pragma unroll
                for (int j = 0; j < 8; j++)
                    if (sc[j] == s) mx = fmaxf(mx, accf[i][j]);
                red[tn][tm * 8 + i] = mx;
            }
            __syncthreads();
            if (tid < 128) {
                float mx = red[0][tid];
                #pragma unroll
                for (int t = 1; t < 16; t++) mx = fmaxf(mx, red[t][tid]);
                atomicMax(&keybuf[s * M + m0 + tid], f2key(mx));
            }
        }
    }
}

// ---------------- launch ----------------
extern "C" void kernel_launch(void* const* d_in, const int* in_sizes, int n_in,
                              void* d_out, int out_size) {
    const float* x    = (const float*)d_in[0];
    const int*   npts = (const int*  )d_in[1];
    const float *W1 = (const float*)d_in[2],  *b1 = (const float*)d_in[3],
                *g1 = (const float*)d_in[4],  *be1= (const float*)d_in[5],
                *m1 = (const float*)d_in[6],  *v1 = (const float*)d_in[7];
    const float *W2 = (const float*)d_in[8],  *b2 = (const float*)d_in[9],
                *g2 = (const float*)d_in[10], *be2= (const float*)d_in[11],
                *m2 = (const float*)d_in[12], *v2 = (const float*)d_in[13];
    const float *W3 = (const float*)d_in[14], *b3 = (const float*)d_in[15],
                *g3 = (const float*)d_in[16], *be3= (const float*)d_in[17],
                *m3 = (const float*)d_in[18], *v3 = (const float*)d_in[19];
    const float *W4 = (const float*)d_in[20], *b4 = (const float*)d_in[21],
                *g4 = (const float*)d_in[22], *be4= (const float*)d_in[23],
                *m4 = (const float*)d_in[24], *v4 = (const float*)d_in[25];

    // launch #1: all setup fused (folds, seg ids, key zeroing)
    setup_kernel<<<1024, 256>>>(npts,
        W1, b1, g1, be1, m1, v1,  W2, b2, g2, be2, m2, v2,
        W3, b3, g3, be3, m3, v3,  W4, b4, g4, be4, m4, v4);

    gemm_kernel<0><<<dim3(NPTS / 128, 2), 256>>>(x);   // #2: f + g-max (layer1 fused)
    fin_g_kernel<<<16, 256>>>();                       // #3
    k_u_kernel<<<32, 256>>>(W3, g3, v3);               // #4
    gemm_kernel<1><<<dim3(NPTS / 128, 4), 256>>>(x);   // #5: h3
    gemm_kernel<2><<<dim3(NPTS / 128, 8), 256>>>(x);   // #6: v-max  (ncu -s 5 lands here)
    fin_v_kernel<<<64, 256>>>((float*)d_out);          // #7
}

// round 6
// speedup vs baseline: 2.4851x; 1.8687x over previous
#include <cuda_runtime.h>
#include <cuda_bf16.h>
#include <cstdint>

#define NPTS 131072
#define BSEG 16
#define EPSF 1e-5f

// ================= device scratch (allocation-free) =================
__device__ __nv_bfloat16 d_a1h[(size_t)NPTS * 128];
__device__ __nv_bfloat16 d_a1l[(size_t)NPTS * 128];
__device__ __nv_bfloat16 d_a2h[(size_t)NPTS * 256];
__device__ __nv_bfloat16 d_a2l[(size_t)NPTS * 256];
__device__ __nv_bfloat16 d_a3h[(size_t)NPTS * 512];
__device__ __nv_bfloat16 d_a3l[(size_t)NPTS * 512];
__device__ __nv_bfloat16 d_w2h[256 * 128],  d_w2l[256 * 128];
__device__ __nv_bfloat16 d_w3h[512 * 256],  d_w3l[512 * 256];
__device__ __nv_bfloat16 d_w4h[1024 * 512], d_w4l[1024 * 512];
__device__ float d_W1c[128 * 4];            // [c][w0,w1,w2,bias]
__device__ float d_b2f[256], d_b3f[512], d_b4f[1024];
__device__ float d_u[512 * BSEG];           // per-segment bias for layer3
__device__ unsigned d_gkey[BSEG * 256];
__device__ float    d_gf  [BSEG * 256];
__device__ unsigned d_vkey[BSEG * 1024];
__device__ int d_seg[NPTS];

// ================= helpers =================
__device__ __forceinline__ unsigned f2key(float f) {
    unsigned u = __float_as_uint(f);
    return (u & 0x80000000u) ? ~u : (u | 0x80000000u);
}
__device__ __forceinline__ float key2f(unsigned k) {
    return (k & 0x80000000u) ? __uint_as_float(k & 0x7FFFFFFFu)
                             : __uint_as_float(~k);
}
__device__ __forceinline__ uint32_t smem_to_u32(const void* p) {
    uint32_t a;
    asm("{ .reg .u64 t; cvta.to.shared.u64 t, %1; cvt.u32.u64 %0, t; }" : "=r"(a) : "l"(p));
    return a;
}
__device__ __forceinline__ void split_bf16(float v, __nv_bfloat16& h, __nv_bfloat16& l) {
    h = __float2bfloat16_rn(v);
    l = __float2bfloat16_rn(v - __bfloat162float(h));
}

// ---- baseline-PTX tensor ops (no sm_103a features) ----
__device__ __forceinline__ void ldsm4(uint32_t (&r)[4], uint32_t addr) {
    asm volatile("ldmatrix.sync.aligned.m8n8.x4.shared.b16 {%0,%1,%2,%3}, [%4];"
                 : "=r"(r[0]), "=r"(r[1]), "=r"(r[2]), "=r"(r[3]) : "r"(addr));
}
__device__ __forceinline__ void mma16816(float (&d)[4], const uint32_t (&a)[4],
                                         uint32_t b0, uint32_t b1) {
    asm volatile("mma.sync.aligned.m16n8k16.row.col.f32.bf16.bf16.f32 "
                 "{%0,%1,%2,%3}, {%4,%5,%6,%7}, {%8,%9}, {%0,%1,%2,%3};"
                 : "+f"(d[0]), "+f"(d[1]), "+f"(d[2]), "+f"(d[3])
                 : "r"(a[0]), "r"(a[1]), "r"(a[2]), "r"(a[3]), "r"(b0), "r"(b1));
}
__device__ __forceinline__ void cpasync16(uint32_t saddr, const void* g) {
    asm volatile("cp.async.cg.shared.global [%0], [%1], 16;" :: "r"(saddr), "l"(g));
}
#define CP_COMMIT() asm volatile("cp.async.commit_group;" ::: "memory")
#define CP_WAIT(N)  asm volatile("cp.async.wait_group %0;" :: "n"(N) : "memory")

// ================= setup =================
__device__ __forceinline__ void fold_split(int t0, int stride,
        const float* __restrict__ W, const float* __restrict__ g, const float* __restrict__ v,
        __nv_bfloat16* wh, __nv_bfloat16* wl, int C, int Kdst, int Ksrc, int Koff) {
    for (int idx = t0; idx < C * Kdst; idx += stride) {
        int c = idx / Kdst, k = idx - c * Kdst;
        float s = g[c] * rsqrtf(v[c] + EPSF);
        split_bf16(s * W[(size_t)c * Ksrc + Koff + k], wh[idx], wl[idx]);
    }
}
__device__ __forceinline__ void fold_bias(int t0, int stride,
        const float* b, const float* g, const float* be, const float* m, const float* v,
        float* bf, int C) {
    for (int i = t0; i < C; i += stride) {
        float s = g[i] * rsqrtf(v[i] + EPSF);
        bf[i] = s * b[i] + be[i] - s * m[i];
    }
}

__global__ void setup_kernel(const int* __restrict__ npts,
    const float* W1, const float* b1, const float* g1, const float* be1, const float* m1, const float* v1,
    const float* W2, const float* b2, const float* g2, const float* be2, const float* m2, const float* v2,
    const float* W3, const float* b3, const float* g3, const float* be3, const float* m3, const float* v3,
    const float* W4, const float* b4, const float* g4, const float* be4, const float* m4, const float* v4) {
    const int stride = gridDim.x * blockDim.x;
    const int t0 = blockIdx.x * blockDim.x + threadIdx.x;

    for (int c = t0; c < 128; c += stride) {
        float s = g1[c] * rsqrtf(v1[c] + EPSF);
        d_W1c[c * 4 + 0] = s * W1[c * 3 + 0];
        d_W1c[c * 4 + 1] = s * W1[c * 3 + 1];
        d_W1c[c * 4 + 2] = s * W1[c * 3 + 2];
        d_W1c[c * 4 + 3] = s * b1[c] + be1[c] - s * m1[c];
    }
    fold_split(t0, stride, W2, g2, v2, d_w2h, d_w2l, 256,  128, 128, 0);
    fold_split(t0, stride, W3, g3, v3, d_w3h, d_w3l, 512,  256, 512, 256);
    fold_split(t0, stride, W4, g4, v4, d_w4h, d_w4l, 1024, 512, 512, 0);
    fold_bias(t0, stride, b2, g2, be2, m2, v2, d_b2f, 256);
    fold_bias(t0, stride, b3, g3, be3, m3, v3, d_b3f, 512);
    fold_bias(t0, stride, b4, g4, be4, m4, v4, d_b4f, 1024);

    int cum[BSEG];
    {
        int a = 0;
        #pragma unroll
        for (int t = 0; t < BSEG; t++) { a += __ldg(&npts[t]); cum[t] = a; }
    }
    for (int j = t0; j < NPTS; j += stride) {
        int s = 0;
        #pragma unroll
        for (int t = 0; t < BSEG - 1; t++) s += (j >= cum[t]);
        d_seg[j] = s;
    }
    for (int i = t0; i < BSEG * 1024; i += stride) d_vkey[i] = 0u;
    for (int i = t0; i < BSEG * 256;  i += stride) d_gkey[i] = 0u;
}

// layer1: one warp per point; lane handles 4 channels
__global__ void h_kernel(const float* __restrict__ x) {
    int pt   = blockIdx.x * 8 + (threadIdx.x >> 5);
    int lane = threadIdx.x & 31;
    float x0 = x[pt], x1 = x[NPTS + pt], x2 = x[2 * NPTS + pt];
    int c0 = lane * 4;
    uint32_t hp[2], lp[2];
    #pragma unroll
    for (int p = 0; p < 2; p++) {
        __nv_bfloat162 hh, ll;
        #pragma unroll
        for (int q = 0; q < 2; q++) {
            int c = c0 + p * 2 + q;
            const float* w = &d_W1c[c * 4];
            float v = fmaxf(w[3] + w[0] * x0 + w[1] * x1 + w[2] * x2, 0.0f);
            __nv_bfloat16 h, l; split_bf16(v, h, l);
            if (q == 0) { hh.x = h; ll.x = l; } else { hh.y = h; ll.y = l; }
        }
        hp[p] = *reinterpret_cast<uint32_t*>(&hh);
        lp[p] = *reinterpret_cast<uint32_t*>(&ll);
    }
    size_t o = (size_t)pt * 128 + c0;
    *reinterpret_cast<uint2*>(&d_a1h[o]) = make_uint2(hp[0], hp[1]);
    *reinterpret_cast<uint2*>(&d_a1l[o]) = make_uint2(lp[0], lp[1]);
}

__global__ void fin_g_kernel() {
    int i = blockIdx.x * blockDim.x + threadIdx.x;
    if (i < BSEG * 256) d_gf[i] = key2f(d_gkey[i]);
}
__global__ void fin_v_kernel(float* __restrict__ out) {
    int i = blockIdx.x * blockDim.x + threadIdx.x;
    if (i < BSEG * 1024) out[i] = key2f(d_vkey[i]);
}
// one warp per (m, s) dot of length 256
__global__ void k_u_kernel(const float* __restrict__ W3,
                           const float* __restrict__ g3,
                           const float* __restrict__ v3) {
    int w = (blockIdx.x * blockDim.x + threadIdx.x) >> 5;
    int lane = threadIdx.x & 31;
    if (w >= 512 * BSEG) return;
    int m = w >> 4, s = w & 15;
    float acc = 0.0f;
    for (int r = lane; r < 256; r += 32)
        acc += W3[(size_t)m * 512 + r] * d_gf[s * 256 + r];
    #pragma unroll
    for (int o = 16; o; o >>= 1) acc += __shfl_xor_sync(0xffffffffu, acc, o);
    if (lane == 0) d_u[m * BSEG + s] = g3[m] * rsqrtf(v3[m] + EPSF) * acc;
}

// ================= mma.sync GEMM =================
// CTA: 128 pts x 128 chans; 8 warps in 4(m) x 2(n); per-warp 32x64.
// K chunks of 32, double-buffered cp.async. 80B-padded smem rows (conflict-free LDSM).
#define TILEB  10240          // 128 rows * 80 B
#define RED_OFF (8 * TILEB)   // float red[8][64]
#define MM_SMEM (RED_OFF + 2048)

template<int CFG>
__global__ void __launch_bounds__(256) mm_kernel() {
    constexpr int K    = (CFG == 0) ? 128 : (CFG == 1) ? 256 : 512;
    constexpr int MOUT = (CFG == 0) ? 256 : (CFG == 1) ? 512 : 1024;
    constexpr int KC   = K / 32;
    constexpr bool SEGMAX = (CFG != 1);
    constexpr bool STORE  = (CFG != 2);

    const __nv_bfloat16* __restrict__ Ah = (CFG == 0) ? d_a1h : (CFG == 1) ? d_a2h : d_a3h;
    const __nv_bfloat16* __restrict__ Al = (CFG == 0) ? d_a1l : (CFG == 1) ? d_a2l : d_a3l;
    const __nv_bfloat16* __restrict__ Bh = (CFG == 0) ? d_w2h : (CFG == 1) ? d_w3h : d_w4h;
    const __nv_bfloat16* __restrict__ Bl = (CFG == 0) ? d_w2l : (CFG == 1) ? d_w3l : d_w4l;
    const float* __restrict__ bias = (CFG == 0) ? d_b2f : (CFG == 1) ? d_b3f : d_b4f;
    __nv_bfloat16* Oh = (CFG == 0) ? d_a2h : d_a3h;
    __nv_bfloat16* Ol = (CFG == 0) ? d_a2l : d_a3l;
    unsigned* key = (CFG == 0) ? d_gkey : d_vkey;

    extern __shared__ char smem[];
    const uint32_t sb = smem_to_u32(smem);
    const int tid = threadIdx.x, wid = tid >> 5, lane = tid & 31;
    const int wm = wid & 3, wn = wid >> 2;
    const int n0 = blockIdx.x * 128;
    const int pt0 = blockIdx.y * 128;

    float acc[2][8][4];
    #pragma unroll
    for (int mi = 0; mi < 2; mi++)
        #pragma unroll
        for (int nt = 0; nt < 8; nt++)
            #pragma unroll
            for (int q = 0; q < 4; q++) acc[mi][nt][q] = 0.0f;

    // ---- async load of one K32 chunk into buffer ----
    auto load_chunk = [&](int kc, int buf) {
        const int k0 = kc * 32;
        #pragma unroll
        for (int t = 0; t < 4; t++) {
            const __nv_bfloat16* base = (t == 0) ? Ah : (t == 1) ? Al : (t == 2) ? Bh : Bl;
            const size_t row0 = (t < 2) ? (size_t)pt0 : (size_t)n0;
            #pragma unroll
            for (int i = 0; i < 2; i++) {
                int idx = i * 256 + tid;          // 0..511
                int row = idx >> 2, c4 = idx & 3; // c4: 16B chunk within 64B of data
                const void* g = base + (row0 + row) * (size_t)K + k0 + c4 * 8;
                uint32_t s = sb + (uint32_t)(buf * 4 + t) * TILEB + row * 80 + c4 * 16;
                cpasync16(s, g);
            }
        }
        CP_COMMIT();
    };

    auto compute = [&](int buf) {
        const uint32_t bb = sb + (uint32_t)(buf * 4) * TILEB;
        #pragma unroll
        for (int kk = 0; kk < 2; kk++) {
            const uint32_t col = (uint32_t)((lane >> 4) * 16 + kk * 32);  // bytes
            uint32_t a_h[2][4], a_l[2][4];
            #pragma unroll
            for (int mi = 0; mi < 2; mi++) {
                uint32_t row = (uint32_t)(wm * 32 + mi * 16 + (lane & 15));
                ldsm4(a_h[mi], bb + 0 * TILEB + row * 80 + col);
                ldsm4(a_l[mi], bb + 1 * TILEB + row * 80 + col);
            }
            #pragma unroll
            for (int ntile = 0; ntile < 4; ntile++) {
                uint32_t row = (uint32_t)(wn * 64 + ntile * 16 + (lane & 15));
                uint32_t b_h[4], b_l[4];
                ldsm4(b_h, bb + 2 * TILEB + row * 80 + col);
                ldsm4(b_l, bb + 3 * TILEB + row * 80 + col);
                #pragma unroll
                for (int mi = 0; mi < 2; mi++) {
                    mma16816(acc[mi][ntile * 2 + 0], a_h[mi], b_h[0], b_h[2]);
                    mma16816(acc[mi][ntile * 2 + 0], a_h[mi], b_l[0], b_l[2]);
                    mma16816(acc[mi][ntile * 2 + 0], a_l[mi], b_h[0], b_h[2]);
                    mma16816(acc[mi][ntile * 2 + 1], a_h[mi], b_h[1], b_h[3]);
                    mma16816(acc[mi][ntile * 2 + 1], a_h[mi], b_l[1], b_l[3]);
                    mma16816(acc[mi][ntile * 2 + 1], a_l[mi], b_h[1], b_h[3]);
                }
            }
        }
    };

    load_chunk(0, 0);
    #pragma unroll 1
    for (int kc = 0; kc < KC; kc++) {
        if (kc + 1 < KC) {
            load_chunk(kc + 1, (kc + 1) & 1);
            CP_WAIT(1);
        } else {
            CP_WAIT(0);
        }
        __syncthreads();
        compute(kc & 1);
        __syncthreads();
    }

    // ---- epilogue ----
    int ptr_[4], sg[4];
    #pragma unroll
    for (int mi = 0; mi < 2; mi++)
        #pragma unroll
        for (int h = 0; h < 2; h++) {
            int p = pt0 + wm * 32 + mi * 16 + (lane >> 2) + h * 8;
            ptr_[mi * 2 + h] = p;
            sg[mi * 2 + h] = d_seg[p];
        }
    const int cbase = n0 + wn * 64 + (lane & 3) * 2;

    #pragma unroll
    for (int mi = 0; mi < 2; mi++) {
        #pragma unroll
        for (int h = 0; h < 2; h++) {
            const int p = ptr_[mi * 2 + h];
            const int seg = sg[mi * 2 + h];
            #pragma unroll
            for (int nt = 0; nt < 8; nt++) {
                const int c = cbase + nt * 8;
                float v0 = acc[mi][nt][h * 2 + 0] + __ldg(&bias[c]);
                float v1 = acc[mi][nt][h * 2 + 1] + __ldg(&bias[c + 1]);
                if (CFG == 1) {
                    v0 = fmaxf(v0 + d_u[c * BSEG + seg], 0.0f);
                    v1 = fmaxf(v1 + d_u[(c + 1) * BSEG + seg], 0.0f);
                }
                acc[mi][nt][h * 2 + 0] = v0;
                acc[mi][nt][h * 2 + 1] = v1;
                if (STORE) {
                    __nv_bfloat162 hh, ll;
                    split_bf16(v0, hh.x, ll.x);
                    split_bf16(v1, hh.y, ll.y);
                    size_t o = (size_t)p * MOUT + c;
                    *reinterpret_cast<uint32_t*>(&Oh[o]) = *reinterpret_cast<uint32_t*>(&hh);
                    *reinterpret_cast<uint32_t*>(&Ol[o]) = *reinterpret_cast<uint32_t*>(&ll);
                }
            }
        }
    }

    if (SEGMAX) {
        float* red = reinterpret_cast<float*>(smem + RED_OFF);
        const int s_lo = d_seg[pt0], s_hi = d_seg[pt0 + 127];
        const int np = (s_lo == s_hi) ? 1 : 2;
        for (int pass = 0; pass < np; pass++) {
            const int s = pass ? s_hi : s_lo;
            float cm[8][2];
            #pragma unroll
            for (int nt = 0; nt < 8; nt++) { cm[nt][0] = -3.402823466e38f; cm[nt][1] = -3.402823466e38f; }
            #pragma unroll
            for (int mi = 0; mi < 2; mi++)
                #pragma unroll
                for (int h = 0; h < 2; h++)
                    if (sg[mi * 2 + h] == s) {
                        #pragma unroll
                        for (int nt = 0; nt < 8; nt++) {
                            cm[nt][0] = fmaxf(cm[nt][0], acc[mi][nt][h * 2 + 0]);
                            cm[nt][1] = fmaxf(cm[nt][1], acc[mi][nt][h * 2 + 1]);
                        }
                    }
            #pragma unroll
            for (int o = 4; o < 32; o <<= 1)
                #pragma unroll
                for (int nt = 0; nt < 8; nt++) {
                    cm[nt][0] = fmaxf(cm[nt][0], __shfl_xor_sync(0xffffffffu, cm[nt][0], o));
                    cm[nt][1] = fmaxf(cm[nt][1], __shfl_xor_sync(0xffffffffu, cm[nt][1], o));
                }
            __syncthreads();   // red reuse across passes
            if ((lane >> 2) == 0) {
                #pragma unroll
                for (int nt = 0; nt < 8; nt++) {
                    red[wid * 64 + nt * 8 + (lane & 3) * 2 + 0] = cm[nt][0];
                    red[wid * 64 + nt * 8 + (lane & 3) * 2 + 1] = cm[nt][1];
                }
            }
            __syncthreads();
            if ((wid & 3) == 0) {   // wid 0 (wn=0) and wid 4 (wn=1)
                const int wgrp = wid >> 2;
                #pragma unroll
                for (int cc = 0; cc < 2; cc++) {
                    const int col = lane * 2 + cc;
                    float m = red[(wgrp * 4 + 0) * 64 + col];
                    #pragma unroll
                    for (int w = 1; w < 4; w++)
                        m = fmaxf(m, red[(wgrp * 4 + w) * 64 + col]);
                    atomicMax(&key[s * MOUT + n0 + wgrp * 64 + col], f2key(m));
                }
            }
        }
    }
}

// ================= launch =================
extern "C" void kernel_launch(void* const* d_in, const int* in_sizes, int n_in,
                              void* d_out, int out_size) {
    const float* x    = (const float*)d_in[0];
    const int*   npts = (const int*  )d_in[1];
    const float *W1 = (const float*)d_in[2],  *b1 = (const float*)d_in[3],
                *g1 = (const float*)d_in[4],  *be1= (const float*)d_in[5],
                *m1 = (const float*)d_in[6],  *v1 = (const float*)d_in[7];
    const float *W2 = (const float*)d_in[8],  *b2 = (const float*)d_in[9],
                *g2 = (const float*)d_in[10], *be2= (const float*)d_in[11],
                *m2 = (const float*)d_in[12], *v2 = (const float*)d_in[13];
    const float *W3 = (const float*)d_in[14], *b3 = (const float*)d_in[15],
                *g3 = (const float*)d_in[16], *be3= (const float*)d_in[17],
                *m3 = (const float*)d_in[18], *v3 = (const float*)d_in[19];
    const float *W4 = (const float*)d_in[20], *b4 = (const float*)d_in[21],
                *g4 = (const float*)d_in[22], *be4= (const float*)d_in[23],
                *m4 = (const float*)d_in[24], *v4 = (const float*)d_in[25];

    cudaFuncSetAttribute(mm_kernel<0>, cudaFuncAttributeMaxDynamicSharedMemorySize, MM_SMEM);
    cudaFuncSetAttribute(mm_kernel<1>, cudaFuncAttributeMaxDynamicSharedMemorySize, MM_SMEM);
    cudaFuncSetAttribute(mm_kernel<2>, cudaFuncAttributeMaxDynamicSharedMemorySize, MM_SMEM);

    setup_kernel<<<512, 256>>>(npts,
        W1, b1, g1, be1, m1, v1,  W2, b2, g2, be2, m2, v2,
        W3, b3, g3, be3, m3, v3,  W4, b4, g4, be4, m4, v4);
    h_kernel<<<NPTS / 8, 256>>>(x);

    mm_kernel<0><<<dim3(2, NPTS / 128), 256, MM_SMEM>>>();   // f = W2 h   (+ g segmax)
    fin_g_kernel<<<16, 256>>>();
    k_u_kernel<<<1024, 256>>>(W3, g3, v3);
    mm_kernel<1><<<dim3(4, NPTS / 128), 256, MM_SMEM>>>();   // h3 = relu(W3b f + u)
    mm_kernel<2><<<dim3(8, NPTS / 128), 256, MM_SMEM>>>();   // v = segmax(W4 h3)
    fin_v_kernel<<<64, 256>>>((float*)d_out);
}

// round 7
// speedup vs baseline: 3.4810x; 1.4007x over previous
#include <cuda_runtime.h>
#include <cuda_fp16.h>
#include <cstdint>

#define NPTS 131072
#define BSEG 16
#define EPSF 1e-5f

// ================= device scratch (allocation-free) =================
// activations: single fp16, point-major [pt][k]
__device__ __half d_a1[(size_t)NPTS * 128];
__device__ __half d_a2[(size_t)NPTS * 256];
__device__ __half d_a3[(size_t)NPTS * 512];
// BN-folded weights [Cout][Cin], fp16 hi/lo split
__device__ __half d_w2h[256 * 128],  d_w2l[256 * 128];
__device__ __half d_w3h[512 * 256],  d_w3l[512 * 256];
__device__ __half d_w4h[1024 * 512], d_w4l[1024 * 512];
__device__ float d_W1c[128 * 4];            // [c][w0,w1,w2,bias]
__device__ float d_b2f[256], d_b3f[512], d_b4f[1024];
__device__ float d_u[512 * BSEG];           // per-segment bias for layer3
__device__ unsigned d_gkey[BSEG * 256];
__device__ float    d_gf  [BSEG * 256];
__device__ unsigned d_vkey[BSEG * 1024];
__device__ int d_seg[NPTS];

// ================= helpers =================
__device__ __forceinline__ unsigned f2key(float f) {
    unsigned u = __float_as_uint(f);
    return (u & 0x80000000u) ? ~u : (u | 0x80000000u);
}
__device__ __forceinline__ float key2f(unsigned k) {
    return (k & 0x80000000u) ? __uint_as_float(k & 0x7FFFFFFFu)
                             : __uint_as_float(~k);
}
__device__ __forceinline__ uint32_t smem_to_u32(const void* p) {
    uint32_t a;
    asm("{ .reg .u64 t; cvta.to.shared.u64 t, %1; cvt.u32.u64 %0, t; }" : "=r"(a) : "l"(p));
    return a;
}
__device__ __forceinline__ void split_half(float v, __half& h, __half& l) {
    h = __float2half_rn(v);
    l = __float2half_rn(v - __half2float(h));
}

// ---- baseline-PTX tensor ops ----
__device__ __forceinline__ void ldsm4(uint32_t (&r)[4], uint32_t addr) {
    asm volatile("ldmatrix.sync.aligned.m8n8.x4.shared.b16 {%0,%1,%2,%3}, [%4];"
                 : "=r"(r[0]), "=r"(r[1]), "=r"(r[2]), "=r"(r[3]) : "r"(addr));
}
__device__ __forceinline__ void mma16816(float (&d)[4], const uint32_t (&a)[4],
                                         uint32_t b0, uint32_t b1) {
    asm volatile("mma.sync.aligned.m16n8k16.row.col.f32.f16.f16.f32 "
                 "{%0,%1,%2,%3}, {%4,%5,%6,%7}, {%8,%9}, {%0,%1,%2,%3};"
                 : "+f"(d[0]), "+f"(d[1]), "+f"(d[2]), "+f"(d[3])
                 : "r"(a[0]), "r"(a[1]), "r"(a[2]), "r"(a[3]), "r"(b0), "r"(b1));
}
__device__ __forceinline__ void cpasync16(uint32_t saddr, const void* g) {
    asm volatile("cp.async.cg.shared.global [%0], [%1], 16;" :: "r"(saddr), "l"(g));
}
#define CP_COMMIT() asm volatile("cp.async.commit_group;" ::: "memory")
#define CP_WAIT(N)  asm volatile("cp.async.wait_group %0;" :: "n"(N) : "memory")

// ================= setup =================
__device__ __forceinline__ void fold_split(int t0, int stride,
        const float* __restrict__ W, const float* __restrict__ g, const float* __restrict__ v,
        __half* wh, __half* wl, int C, int Kdst, int Ksrc, int Koff) {
    for (int idx = t0; idx < C * Kdst; idx += stride) {
        int c = idx / Kdst, k = idx - c * Kdst;
        float s = g[c] * rsqrtf(v[c] + EPSF);
        split_half(s * W[(size_t)c * Ksrc + Koff + k], wh[idx], wl[idx]);
    }
}
__device__ __forceinline__ void fold_bias(int t0, int stride,
        const float* b, const float* g, const float* be, const float* m, const float* v,
        float* bf, int C) {
    for (int i = t0; i < C; i += stride) {
        float s = g[i] * rsqrtf(v[i] + EPSF);
        bf[i] = s * b[i] + be[i] - s * m[i];
    }
}

__global__ void setup_kernel(const int* __restrict__ npts,
    const float* W1, const float* b1, const float* g1, const float* be1, const float* m1, const float* v1,
    const float* W2, const float* b2, const float* g2, const float* be2, const float* m2, const float* v2,
    const float* W3, const float* b3, const float* g3, const float* be3, const float* m3, const float* v3,
    const float* W4, const float* b4, const float* g4, const float* be4, const float* m4, const float* v4) {
    const int stride = gridDim.x * blockDim.x;
    const int t0 = blockIdx.x * blockDim.x + threadIdx.x;

    for (int c = t0; c < 128; c += stride) {
        float s = g1[c] * rsqrtf(v1[c] + EPSF);
        d_W1c[c * 4 + 0] = s * W1[c * 3 + 0];
        d_W1c[c * 4 + 1] = s * W1[c * 3 + 1];
        d_W1c[c * 4 + 2] = s * W1[c * 3 + 2];
        d_W1c[c * 4 + 3] = s * b1[c] + be1[c] - s * m1[c];
    }
    fold_split(t0, stride, W2, g2, v2, d_w2h, d_w2l, 256,  128, 128, 0);
    fold_split(t0, stride, W3, g3, v3, d_w3h, d_w3l, 512,  256, 512, 256);
    fold_split(t0, stride, W4, g4, v4, d_w4h, d_w4l, 1024, 512, 512, 0);
    fold_bias(t0, stride, b2, g2, be2, m2, v2, d_b2f, 256);
    fold_bias(t0, stride, b3, g3, be3, m3, v3, d_b3f, 512);
    fold_bias(t0, stride, b4, g4, be4, m4, v4, d_b4f, 1024);

    int cum[BSEG];
    {
        int a = 0;
        #pragma unroll
        for (int t = 0; t < BSEG; t++) { a += __ldg(&npts[t]); cum[t] = a; }
    }
    for (int j = t0; j < NPTS; j += stride) {
        int s = 0;
        #pragma unroll
        for (int t = 0; t < BSEG - 1; t++) s += (j >= cum[t]);
        d_seg[j] = s;
    }
    for (int i = t0; i < BSEG * 1024; i += stride) d_vkey[i] = 0u;
    for (int i = t0; i < BSEG * 256;  i += stride) d_gkey[i] = 0u;
}

// layer1: one warp per point; lane handles 4 channels
__global__ void h_kernel(const float* __restrict__ x) {
    int pt   = blockIdx.x * 8 + (threadIdx.x >> 5);
    int lane = threadIdx.x & 31;
    float x0 = x[pt], x1 = x[NPTS + pt], x2 = x[2 * NPTS + pt];
    int c0 = lane * 4;
    uint32_t pk[2];
    #pragma unroll
    for (int p = 0; p < 2; p++) {
        __half2 hh;
        #pragma unroll
        for (int q = 0; q < 2; q++) {
            int c = c0 + p * 2 + q;
            const float* w = &d_W1c[c * 4];
            float v = fmaxf(w[3] + w[0] * x0 + w[1] * x1 + w[2] * x2, 0.0f);
            if (q == 0) hh.x = __float2half_rn(v); else hh.y = __float2half_rn(v);
        }
        pk[p] = *reinterpret_cast<uint32_t*>(&hh);
    }
    *reinterpret_cast<uint2*>(&d_a1[(size_t)pt * 128 + c0]) = make_uint2(pk[0], pk[1]);
}

__global__ void fin_g_kernel() {
    int i = blockIdx.x * blockDim.x + threadIdx.x;
    if (i < BSEG * 256) d_gf[i] = key2f(d_gkey[i]);
}
__global__ void fin_v_kernel(float* __restrict__ out) {
    int i = blockIdx.x * blockDim.x + threadIdx.x;
    if (i < BSEG * 1024) out[i] = key2f(d_vkey[i]);
}
// one warp per (m, s) dot of length 256
__global__ void k_u_kernel(const float* __restrict__ W3,
                           const float* __restrict__ g3,
                           const float* __restrict__ v3) {
    int w = (blockIdx.x * blockDim.x + threadIdx.x) >> 5;
    int lane = threadIdx.x & 31;
    if (w >= 512 * BSEG) return;
    int m = w >> 4, s = w & 15;
    float acc = 0.0f;
    for (int r = lane; r < 256; r += 32)
        acc += W3[(size_t)m * 512 + r] * d_gf[s * 256 + r];
    #pragma unroll
    for (int o = 16; o; o >>= 1) acc += __shfl_xor_sync(0xffffffffu, acc, o);
    if (lane == 0) d_u[m * BSEG + s] = g3[m] * rsqrtf(v3[m] + EPSF) * acc;
}

// ================= mma.sync GEMM (fp16, asymmetric split, 3-stage pipeline) =================
// CTA: 128 pts x 128 chans; 8 warps 4(m) x 2(n); per-warp 32x64.
// K chunks of 32; stages=3; tiles per chunk: A, Bh, Bl. 80B-padded rows.
#define TILEB   10240                 // 128 rows * 80 B
#define NSTAGE  3
#define RED_OFF (NSTAGE * 3 * TILEB)  // float red[8][64]
#define MM_SMEM (RED_OFF + 2048)

template<int CFG>
__global__ void __launch_bounds__(256) mm_kernel() {
    constexpr int K    = (CFG == 0) ? 128 : (CFG == 1) ? 256 : 512;
    constexpr int MOUT = (CFG == 0) ? 256 : (CFG == 1) ? 512 : 1024;
    constexpr int KC   = K / 32;
    constexpr bool SEGMAX = (CFG != 1);
    constexpr bool STORE  = (CFG != 2);

    const __half* __restrict__ Ain = (CFG == 0) ? d_a1 : (CFG == 1) ? d_a2 : d_a3;
    const __half* __restrict__ Bh  = (CFG == 0) ? d_w2h : (CFG == 1) ? d_w3h : d_w4h;
    const __half* __restrict__ Bl  = (CFG == 0) ? d_w2l : (CFG == 1) ? d_w3l : d_w4l;
    const float* __restrict__ bias = (CFG == 0) ? d_b2f : (CFG == 1) ? d_b3f : d_b4f;
    __half* Oa = (CFG == 0) ? d_a2 : d_a3;
    unsigned* key = (CFG == 0) ? d_gkey : d_vkey;

    extern __shared__ char smem[];
    const uint32_t sb = smem_to_u32(smem);
    const int tid = threadIdx.x, wid = tid >> 5, lane = tid & 31;
    const int wm = wid & 3, wn = wid >> 2;
    const int n0 = blockIdx.x * 128;
    const int pt0 = blockIdx.y * 128;

    float acc[2][8][4];
    #pragma unroll
    for (int mi = 0; mi < 2; mi++)
        #pragma unroll
        for (int nt = 0; nt < 8; nt++)
            #pragma unroll
            for (int q = 0; q < 4; q++) acc[mi][nt][q] = 0.0f;

    auto load_chunk = [&](int kc, int buf) {
        const int k0 = kc * 32;
        #pragma unroll
        for (int t = 0; t < 3; t++) {
            const __half* base = (t == 0) ? Ain : (t == 1) ? Bh : Bl;
            const size_t row0 = (t == 0) ? (size_t)pt0 : (size_t)n0;
            #pragma unroll
            for (int i = 0; i < 2; i++) {
                int idx = i * 256 + tid;          // 0..511
                int row = idx >> 2, c4 = idx & 3;
                const void* g = base + (row0 + row) * (size_t)K + k0 + c4 * 8;
                uint32_t s = sb + (uint32_t)(buf * 3 + t) * TILEB + row * 80 + c4 * 16;
                cpasync16(s, g);
            }
        }
        CP_COMMIT();
    };

    auto compute = [&](int buf) {
        const uint32_t bb = sb + (uint32_t)(buf * 3) * TILEB;
        #pragma unroll
        for (int kk = 0; kk < 2; kk++) {
            const uint32_t col = (uint32_t)((lane >> 4) * 16 + kk * 32);  // bytes
            uint32_t a_f[2][4];
            #pragma unroll
            for (int mi = 0; mi < 2; mi++) {
                uint32_t row = (uint32_t)(wm * 32 + mi * 16 + (lane & 15));
                ldsm4(a_f[mi], bb + row * 80 + col);
            }
            #pragma unroll
            for (int ntile = 0; ntile < 4; ntile++) {
                uint32_t row = (uint32_t)(wn * 64 + ntile * 16 + (lane & 15));
                uint32_t b_h[4], b_l[4];
                ldsm4(b_h, bb + 1 * TILEB + row * 80 + col);
                ldsm4(b_l, bb + 2 * TILEB + row * 80 + col);
                #pragma unroll
                for (int mi = 0; mi < 2; mi++) {
                    mma16816(acc[mi][ntile * 2 + 0], a_f[mi], b_h[0], b_h[2]);
                    mma16816(acc[mi][ntile * 2 + 0], a_f[mi], b_l[0], b_l[2]);
                    mma16816(acc[mi][ntile * 2 + 1], a_f[mi], b_h[1], b_h[3]);
                    mma16816(acc[mi][ntile * 2 + 1], a_f[mi], b_l[1], b_l[3]);
                }
            }
        }
    };

    // 3-stage pipeline: one sync per chunk
    load_chunk(0, 0);
    load_chunk(1, 1);
    #pragma unroll 1
    for (int kc = 0; kc < KC; kc++) {
        CP_WAIT(1);                 // chunk kc resident (kc+1 may be in flight)
        __syncthreads();            // all warps done with compute(kc-1) -> buf (kc+2)%3 free
        if (kc + 2 < KC) load_chunk(kc + 2, (kc + 2) % NSTAGE);
        compute(kc % NSTAGE);
    }

    // ---- epilogue ----
    int ptr_[4], sg[4];
    #pragma unroll
    for (int mi = 0; mi < 2; mi++)
        #pragma unroll
        for (int h = 0; h < 2; h++) {
            int p = pt0 + wm * 32 + mi * 16 + (lane >> 2) + h * 8;
            ptr_[mi * 2 + h] = p;
            sg[mi * 2 + h] = d_seg[p];
        }
    const int cbase = n0 + wn * 64 + (lane & 3) * 2;

    #pragma unroll
    for (int mi = 0; mi < 2; mi++) {
        #pragma unroll
        for (int h = 0; h < 2; h++) {
            const int p = ptr_[mi * 2 + h];
            const int seg = sg[mi * 2 + h];
            #pragma unroll
            for (int nt = 0; nt < 8; nt++) {
                const int c = cbase + nt * 8;
                float v0 = acc[mi][nt][h * 2 + 0] + __ldg(&bias[c]);
                float v1 = acc[mi][nt][h * 2 + 1] + __ldg(&bias[c + 1]);
                if (CFG == 1) {
                    v0 = fmaxf(v0 + d_u[c * BSEG + seg], 0.0f);
                    v1 = fmaxf(v1 + d_u[(c + 1) * BSEG + seg], 0.0f);
                }
                acc[mi][nt][h * 2 + 0] = v0;
                acc[mi][nt][h * 2 + 1] = v1;
                if (STORE) {
                    __half2 hh;
                    hh.x = __float2half_rn(v0);
                    hh.y = __float2half_rn(v1);
                    *reinterpret_cast<uint32_t*>(&Oa[(size_t)p * MOUT + c]) =
                        *reinterpret_cast<uint32_t*>(&hh);
                }
            }
        }
    }

    if (SEGMAX) {
        float* red = reinterpret_cast<float*>(smem + RED_OFF);
        const int s_lo = d_seg[pt0], s_hi = d_seg[pt0 + 127];
        const int np = (s_lo == s_hi) ? 1 : 2;
        for (int pass = 0; pass < np; pass++) {
            const int s = pass ? s_hi : s_lo;
            float cm[8][2];
            #pragma unroll
            for (int nt = 0; nt < 8; nt++) { cm[nt][0] = -3.402823466e38f; cm[nt][1] = -3.402823466e38f; }
            #pragma unroll
            for (int mi = 0; mi < 2; mi++)
                #pragma unroll
                for (int h = 0; h < 2; h++)
                    if (sg[mi * 2 + h] == s) {
                        #pragma unroll
                        for (int nt = 0; nt < 8; nt++) {
                            cm[nt][0] = fmaxf(cm[nt][0], acc[mi][nt][h * 2 + 0]);
                            cm[nt][1] = fmaxf(cm[nt][1], acc[mi][nt][h * 2 + 1]);
                        }
                    }
            #pragma unroll
            for (int o = 4; o < 32; o <<= 1)
                #pragma unroll
                for (int nt = 0; nt < 8; nt++) {
                    cm[nt][0] = fmaxf(cm[nt][0], __shfl_xor_sync(0xffffffffu, cm[nt][0], o));
                    cm[nt][1] = fmaxf(cm[nt][1], __shfl_xor_sync(0xffffffffu, cm[nt][1], o));
                }
            __syncthreads();
            if ((lane >> 2) == 0) {
                #pragma unroll
                for (int nt = 0; nt < 8; nt++) {
                    red[wid * 64 + nt * 8 + (lane & 3) * 2 + 0] = cm[nt][0];
                    red[wid * 64 + nt * 8 + (lane & 3) * 2 + 1] = cm[nt][1];
                }
            }
            __syncthreads();
            if ((wid & 3) == 0) {
                const int wgrp = wid >> 2;
                #pragma unroll
                for (int cc = 0; cc < 2; cc++) {
                    const int col = lane * 2 + cc;
                    float m = red[(wgrp * 4 + 0) * 64 + col];
                    #pragma unroll
                    for (int w = 1; w < 4; w++)
                        m = fmaxf(m, red[(wgrp * 4 + w) * 64 + col]);
                    atomicMax(&key[s * MOUT + n0 + wgrp * 64 + col], f2key(m));
                }
            }
        }
    }
}

// ================= launch =================
extern "C" void kernel_launch(void* const* d_in, const int* in_sizes, int n_in,
                              void* d_out, int out_size) {
    const float* x    = (const float*)d_in[0];
    const int*   npts = (const int*  )d_in[1];
    const float *W1 = (const float*)d_in[2],  *b1 = (const float*)d_in[3],
                *g1 = (const float*)d_in[4],  *be1= (const float*)d_in[5],
                *m1 = (const float*)d_in[6],  *v1 = (const float*)d_in[7];
    const float *W2 = (const float*)d_in[8],  *b2 = (const float*)d_in[9],
                *g2 = (const float*)d_in[10], *be2= (const float*)d_in[11],
                *m2 = (const float*)d_in[12], *v2 = (const float*)d_in[13];
    const float *W3 = (const float*)d_in[14], *b3 = (const float*)d_in[15],
                *g3 = (const float*)d_in[16], *be3= (const float*)d_in[17],
                *m3 = (const float*)d_in[18], *v3 = (const float*)d_in[19];
    const float *W4 = (const float*)d_in[20], *b4 = (const float*)d_in[21],
                *g4 = (const float*)d_in[22], *be4= (const float*)d_in[23],
                *m4 = (const float*)d_in[24], *v4 = (const float*)d_in[25];

    cudaFuncSetAttribute(mm_kernel<0>, cudaFuncAttributeMaxDynamicSharedMemorySize, MM_SMEM);
    cudaFuncSetAttribute(mm_kernel<1>, cudaFuncAttributeMaxDynamicSharedMemorySize, MM_SMEM);
    cudaFuncSetAttribute(mm_kernel<2>, cudaFuncAttributeMaxDynamicSharedMemorySize, MM_SMEM);

    setup_kernel<<<512, 256>>>(npts,
        W1, b1, g1, be1, m1, v1,  W2, b2, g2, be2, m2, v2,
        W3, b3, g3, be3, m3, v3,  W4, b4, g4, be4, m4, v4);
    h_kernel<<<NPTS / 8, 256>>>(x);

    mm_kernel<0><<<dim3(2, NPTS / 128), 256, MM_SMEM>>>();   // f = W2 h   (+ g segmax)
    fin_g_kernel<<<16, 256>>>();
    k_u_kernel<<<1024, 256>>>(W3, g3, v3);
    mm_kernel<1><<<dim3(4, NPTS / 128), 256, MM_SMEM>>>();   // h3 = relu(W3b f + u)
    mm_kernel<2><<<dim3(8, NPTS / 128), 256, MM_SMEM>>>();   // v = segmax(W4 h3)
    fin_v_kernel<<<64, 256>>>((float*)d_out);
}

// round 8
// speedup vs baseline: 4.7769x; 1.3723x over previous
#include <cuda_runtime.h>
#include <cuda_fp16.h>
#include <cstdint>

#define NPTS 131072
#define BSEG 16
#define EPSF 1e-5f

// ================= device scratch (allocation-free) =================
// activations: single fp16, point-major [pt][k]
__device__ __half d_a1[(size_t)NPTS * 128];
__device__ __half d_a2[(size_t)NPTS * 256];
__device__ __half d_a3[(size_t)NPTS * 512];
// BN-folded weights [Cout][Cin], single fp16
__device__ __half d_w2[256 * 128];
__device__ __half d_w3[512 * 256];
__device__ __half d_w4[1024 * 512];
__device__ float d_W1c[128 * 4];            // [c][w0,w1,w2,bias]
__device__ float d_b2f[256], d_b3f[512], d_b4f[1024];
__device__ float d_u[512 * BSEG];           // per-segment bias for layer3
__device__ unsigned d_gkey[BSEG * 256];
__device__ float    d_gf  [BSEG * 256];
__device__ unsigned d_vkey[BSEG * 1024];
__device__ int d_seg[NPTS];

// ================= helpers =================
__device__ __forceinline__ unsigned f2key(float f) {
    unsigned u = __float_as_uint(f);
    return (u & 0x80000000u) ? ~u : (u | 0x80000000u);
}
__device__ __forceinline__ float key2f(unsigned k) {
    return (k & 0x80000000u) ? __uint_as_float(k & 0x7FFFFFFFu)
                             : __uint_as_float(~k);
}
__device__ __forceinline__ uint32_t smem_to_u32(const void* p) {
    uint32_t a;
    asm("{ .reg .u64 t; cvta.to.shared.u64 t, %1; cvt.u32.u64 %0, t; }" : "=r"(a) : "l"(p));
    return a;
}

// ---- baseline-PTX tensor ops ----
__device__ __forceinline__ void ldsm4(uint32_t (&r)[4], uint32_t addr) {
    asm volatile("ldmatrix.sync.aligned.m8n8.x4.shared.b16 {%0,%1,%2,%3}, [%4];"
                 : "=r"(r[0]), "=r"(r[1]), "=r"(r[2]), "=r"(r[3]) : "r"(addr));
}
__device__ __forceinline__ void mma16816(float (&d)[4], const uint32_t (&a)[4],
                                         uint32_t b0, uint32_t b1) {
    asm volatile("mma.sync.aligned.m16n8k16.row.col.f32.f16.f16.f32 "
                 "{%0,%1,%2,%3}, {%4,%5,%6,%7}, {%8,%9}, {%0,%1,%2,%3};"
                 : "+f"(d[0]), "+f"(d[1]), "+f"(d[2]), "+f"(d[3])
                 : "r"(a[0]), "r"(a[1]), "r"(a[2]), "r"(a[3]), "r"(b0), "r"(b1));
}
__device__ __forceinline__ void cpasync16(uint32_t saddr, const void* g) {
    asm volatile("cp.async.cg.shared.global [%0], [%1], 16;" :: "r"(saddr), "l"(g));
}
#define CP_COMMIT() asm volatile("cp.async.commit_group;" ::: "memory")
#define CP_WAIT(N)  asm volatile("cp.async.wait_group %0;" :: "n"(N) : "memory")

// ================= setup =================
__device__ __forceinline__ void fold_single(int t0, int stride,
        const float* __restrict__ W, const float* __restrict__ g, const float* __restrict__ v,
        __half* wd, int C, int Kdst, int Ksrc, int Koff) {
    for (int idx = t0; idx < C * Kdst; idx += stride) {
        int c = idx / Kdst, k = idx - c * Kdst;
        float s = g[c] * rsqrtf(v[c] + EPSF);
        wd[idx] = __float2half_rn(s * W[(size_t)c * Ksrc + Koff + k]);
    }
}
__device__ __forceinline__ void fold_bias(int t0, int stride,
        const float* b, const float* g, const float* be, const float* m, const float* v,
        float* bf, int C) {
    for (int i = t0; i < C; i += stride) {
        float s = g[i] * rsqrtf(v[i] + EPSF);
        bf[i] = s * b[i] + be[i] - s * m[i];
    }
}

__global__ void setup_kernel(const int* __restrict__ npts,
    const float* W1, const float* b1, const float* g1, const float* be1, const float* m1, const float* v1,
    const float* W2, const float* b2, const float* g2, const float* be2, const float* m2, const float* v2,
    const float* W3, const float* b3, const float* g3, const float* be3, const float* m3, const float* v3,
    const float* W4, const float* b4, const float* g4, const float* be4, const float* m4, const float* v4) {
    const int stride = gridDim.x * blockDim.x;
    const int t0 = blockIdx.x * blockDim.x + threadIdx.x;

    for (int c = t0; c < 128; c += stride) {
        float s = g1[c] * rsqrtf(v1[c] + EPSF);
        d_W1c[c * 4 + 0] = s * W1[c * 3 + 0];
        d_W1c[c * 4 + 1] = s * W1[c * 3 + 1];
        d_W1c[c * 4 + 2] = s * W1[c * 3 + 2];
        d_W1c[c * 4 + 3] = s * b1[c] + be1[c] - s * m1[c];
    }
    fold_single(t0, stride, W2, g2, v2, d_w2, 256,  128, 128, 0);
    fold_single(t0, stride, W3, g3, v3, d_w3, 512,  256, 512, 256);
    fold_single(t0, stride, W4, g4, v4, d_w4, 1024, 512, 512, 0);
    fold_bias(t0, stride, b2, g2, be2, m2, v2, d_b2f, 256);
    fold_bias(t0, stride, b3, g3, be3, m3, v3, d_b3f, 512);
    fold_bias(t0, stride, b4, g4, be4, m4, v4, d_b4f, 1024);

    int cum[BSEG];
    {
        int a = 0;
        #pragma unroll
        for (int t = 0; t < BSEG; t++) { a += __ldg(&npts[t]); cum[t] = a; }
    }
    for (int j = t0; j < NPTS; j += stride) {
        int s = 0;
        #pragma unroll
        for (int t = 0; t < BSEG - 1; t++) s += (j >= cum[t]);
        d_seg[j] = s;
    }
    for (int i = t0; i < BSEG * 1024; i += stride) d_vkey[i] = 0u;
    for (int i = t0; i < BSEG * 256;  i += stride) d_gkey[i] = 0u;
}

// layer1: one warp per point; lane handles 4 channels
__global__ void h_kernel(const float* __restrict__ x) {
    int pt   = blockIdx.x * 8 + (threadIdx.x >> 5);
    int lane = threadIdx.x & 31;
    float x0 = x[pt], x1 = x[NPTS + pt], x2 = x[2 * NPTS + pt];
    int c0 = lane * 4;
    uint32_t pk[2];
    #pragma unroll
    for (int p = 0; p < 2; p++) {
        __half2 hh;
        #pragma unroll
        for (int q = 0; q < 2; q++) {
            int c = c0 + p * 2 + q;
            const float* w = &d_W1c[c * 4];
            float v = fmaxf(w[3] + w[0] * x0 + w[1] * x1 + w[2] * x2, 0.0f);
            if (q == 0) hh.x = __float2half_rn(v); else hh.y = __float2half_rn(v);
        }
        pk[p] = *reinterpret_cast<uint32_t*>(&hh);
    }
    *reinterpret_cast<uint2*>(&d_a1[(size_t)pt * 128 + c0]) = make_uint2(pk[0], pk[1]);
}

__global__ void fin_g_kernel() {
    int i = blockIdx.x * blockDim.x + threadIdx.x;
    if (i < BSEG * 256) d_gf[i] = key2f(d_gkey[i]);
}
__global__ void fin_v_kernel(float* __restrict__ out) {
    int i = blockIdx.x * blockDim.x + threadIdx.x;
    if (i < BSEG * 1024) out[i] = key2f(d_vkey[i]);
}
// one warp per (m, s) dot of length 256
__global__ void k_u_kernel(const float* __restrict__ W3,
                           const float* __restrict__ g3,
                           const float* __restrict__ v3) {
    int w = (blockIdx.x * blockDim.x + threadIdx.x) >> 5;
    int lane = threadIdx.x & 31;
    if (w >= 512 * BSEG) return;
    int m = w >> 4, s = w & 15;
    float acc = 0.0f;
    for (int r = lane; r < 256; r += 32)
        acc += W3[(size_t)m * 512 + r] * d_gf[s * 256 + r];
    #pragma unroll
    for (int o = 16; o; o >>= 1) acc += __shfl_xor_sync(0xffffffffu, acc, o);
    if (lane == 0) d_u[m * BSEG + s] = g3[m] * rsqrtf(v3[m] + EPSF) * acc;
}

// ================= mma.sync GEMM (fp16 x fp16, 64x64 warp tiles) =================
// CTA: 256 pts x 128 chans; 8 warps 4(m) x 2(n); per-warp 64x64.
// K chunks of 32; 3 stages; per chunk: A(256x32) + B(128x32). 80B-padded rows.
#define ATILE   20480                 // 256 rows * 80 B
#define BTILE   10240                 // 128 rows * 80 B
#define STAGEB  (ATILE + BTILE)
#define NSTAGE  3
#define RED_OFF (NSTAGE * STAGEB)     // float red[8][64]
#define MM_SMEM (RED_OFF + 2048)

template<int CFG>
__global__ void __launch_bounds__(256) mm_kernel() {
    constexpr int K    = (CFG == 0) ? 128 : (CFG == 1) ? 256 : 512;
    constexpr int MOUT = (CFG == 0) ? 256 : (CFG == 1) ? 512 : 1024;
    constexpr int KC   = K / 32;
    constexpr bool SEGMAX = (CFG != 1);
    constexpr bool STORE  = (CFG != 2);

    const __half* __restrict__ Ain = (CFG == 0) ? d_a1 : (CFG == 1) ? d_a2 : d_a3;
    const __half* __restrict__ Bw  = (CFG == 0) ? d_w2 : (CFG == 1) ? d_w3 : d_w4;
    const float* __restrict__ bias = (CFG == 0) ? d_b2f : (CFG == 1) ? d_b3f : d_b4f;
    __half* Oa = (CFG == 0) ? d_a2 : d_a3;
    unsigned* key = (CFG == 0) ? d_gkey : d_vkey;

    extern __shared__ char smem[];
    const uint32_t sb = smem_to_u32(smem);
    const int tid = threadIdx.x, wid = tid >> 5, lane = tid & 31;
    const int wm = wid & 3, wn = wid >> 2;
    const int n0 = blockIdx.x * 128;
    const int pt0 = blockIdx.y * 256;

    float acc[4][8][4];
    #pragma unroll
    for (int mi = 0; mi < 4; mi++)
        #pragma unroll
        for (int nt = 0; nt < 8; nt++)
            #pragma unroll
            for (int q = 0; q < 4; q++) acc[mi][nt][q] = 0.0f;

    auto load_chunk = [&](int kc, int buf) {
        const int k0 = kc * 32;
        const uint32_t base = sb + (uint32_t)buf * STAGEB;
        #pragma unroll
        for (int i = 0; i < 4; i++) {                  // A: 256 rows
            int idx = i * 256 + tid;
            int row = idx >> 2, c4 = idx & 3;
            cpasync16(base + row * 80 + c4 * 16,
                      Ain + (size_t)(pt0 + row) * K + k0 + c4 * 8);
        }
        #pragma unroll
        for (int i = 0; i < 2; i++) {                  // B: 128 rows
            int idx = i * 256 + tid;
            int row = idx >> 2, c4 = idx & 3;
            cpasync16(base + ATILE + row * 80 + c4 * 16,
                      Bw + (size_t)(n0 + row) * K + k0 + c4 * 8);
        }
        CP_COMMIT();
    };

    auto compute = [&](int buf) {
        const uint32_t ab = sb + (uint32_t)buf * STAGEB;
        const uint32_t bbB = ab + ATILE;
        #pragma unroll
        for (int kk = 0; kk < 2; kk++) {
            const uint32_t col = (uint32_t)((lane >> 4) * 16 + kk * 32);  // bytes
            uint32_t a_f[4][4];
            #pragma unroll
            for (int mi = 0; mi < 4; mi++) {
                uint32_t row = (uint32_t)(wm * 64 + mi * 16 + (lane & 15));
                ldsm4(a_f[mi], ab + row * 80 + col);
            }
            #pragma unroll
            for (int nt4 = 0; nt4 < 4; nt4++) {
                uint32_t row = (uint32_t)(wn * 64 + nt4 * 16 + (lane & 15));
                uint32_t b_f[4];
                ldsm4(b_f, bbB + row * 80 + col);
                #pragma unroll
                for (int mi = 0; mi < 4; mi++) {
                    mma16816(acc[mi][nt4 * 2 + 0], a_f[mi], b_f[0], b_f[2]);
                    mma16816(acc[mi][nt4 * 2 + 1], a_f[mi], b_f[1], b_f[3]);
                }
            }
        }
    };

    // 3-stage pipeline: one sync per chunk
    load_chunk(0, 0);
    load_chunk(1, 1);
    #pragma unroll 1
    for (int kc = 0; kc < KC; kc++) {
        CP_WAIT(1);
        __syncthreads();
        if (kc + 2 < KC) load_chunk(kc + 2, (kc + 2) % NSTAGE);
        compute(kc % NSTAGE);
    }

    // ---- epilogue ----
    int ptr_[8], sg[8];
    #pragma unroll
    for (int mi = 0; mi < 4; mi++)
        #pragma unroll
        for (int h = 0; h < 2; h++) {
            int p = pt0 + wm * 64 + mi * 16 + (lane >> 2) + h * 8;
            ptr_[mi * 2 + h] = p;
            sg[mi * 2 + h] = d_seg[p];
        }
    const int cbase = n0 + wn * 64 + (lane & 3) * 2;

    #pragma unroll
    for (int mi = 0; mi < 4; mi++) {
        #pragma unroll
        for (int h = 0; h < 2; h++) {
            const int p = ptr_[mi * 2 + h];
            const int seg = sg[mi * 2 + h];
            #pragma unroll
            for (int nt = 0; nt < 8; nt++) {
                const int c = cbase + nt * 8;
                float v0 = acc[mi][nt][h * 2 + 0] + __ldg(&bias[c]);
                float v1 = acc[mi][nt][h * 2 + 1] + __ldg(&bias[c + 1]);
                if (CFG == 1) {
                    v0 = fmaxf(v0 + d_u[c * BSEG + seg], 0.0f);
                    v1 = fmaxf(v1 + d_u[(c + 1) * BSEG + seg], 0.0f);
                }
                acc[mi][nt][h * 2 + 0] = v0;
                acc[mi][nt][h * 2 + 1] = v1;
                if (STORE) {
                    __half2 hh;
                    hh.x = __float2half_rn(v0);
                    hh.y = __float2half_rn(v1);
                    *reinterpret_cast<uint32_t*>(&Oa[(size_t)p * MOUT + c]) =
                        *reinterpret_cast<uint32_t*>(&hh);
                }
            }
        }
    }

    if (SEGMAX) {
        float* red = reinterpret_cast<float*>(smem + RED_OFF);
        const int s_lo = d_seg[pt0], s_hi = d_seg[pt0 + 255];
        const int np = (s_lo == s_hi) ? 1 : 2;
        for (int pass = 0; pass < np; pass++) {
            const int s = pass ? s_hi : s_lo;
            float cm[8][2];
            #pragma unroll
            for (int nt = 0; nt < 8; nt++) { cm[nt][0] = -3.402823466e38f; cm[nt][1] = -3.402823466e38f; }
            #pragma unroll
            for (int mi = 0; mi < 4; mi++)
                #pragma unroll
                for (int h = 0; h < 2; h++)
                    if (sg[mi * 2 + h] == s) {
                        #pragma unroll
                        for (int nt = 0; nt < 8; nt++) {
                            cm[nt][0] = fmaxf(cm[nt][0], acc[mi][nt][h * 2 + 0]);
                            cm[nt][1] = fmaxf(cm[nt][1], acc[mi][nt][h * 2 + 1]);
                        }
                    }
            #pragma unroll
            for (int o = 4; o < 32; o <<= 1)
                #pragma unroll
                for (int nt = 0; nt < 8; nt++) {
                    cm[nt][0] = fmaxf(cm[nt][0], __shfl_xor_sync(0xffffffffu, cm[nt][0], o));
                    cm[nt][1] = fmaxf(cm[nt][1], __shfl_xor_sync(0xffffffffu, cm[nt][1], o));
                }
            __syncthreads();
            if ((lane >> 2) == 0) {
                #pragma unroll
                for (int nt = 0; nt < 8; nt++) {
                    red[wid * 64 + nt * 8 + (lane & 3) * 2 + 0] = cm[nt][0];
                    red[wid * 64 + nt * 8 + (lane & 3) * 2 + 1] = cm[nt][1];
                }
            }
            __syncthreads();
            if ((wid & 3) == 0) {
                const int wgrp = wid >> 2;
                #pragma unroll
                for (int cc = 0; cc < 2; cc++) {
                    const int col = lane * 2 + cc;
                    float m = red[(wgrp * 4 + 0) * 64 + col];
                    #pragma unroll
                    for (int w = 1; w < 4; w++)
                        m = fmaxf(m, red[(wgrp * 4 + w) * 64 + col]);
                    atomicMax(&key[s * MOUT + n0 + wgrp * 64 + col], f2key(m));
                }
            }
        }
    }
}

// ================= launch =================
extern "C" void kernel_launch(void* const* d_in, const int* in_sizes, int n_in,
                              void* d_out, int out_size) {
    const float* x    = (const float*)d_in[0];
    const int*   npts = (const int*  )d_in[1];
    const float *W1 = (const float*)d_in[2],  *b1 = (const float*)d_in[3],
                *g1 = (const float*)d_in[4],  *be1= (const float*)d_in[5],
                *m1 = (const float*)d_in[6],  *v1 = (const float*)d_in[7];
    const float *W2 = (const float*)d_in[8],  *b2 = (const float*)d_in[9],
                *g2 = (const float*)d_in[10], *be2= (const float*)d_in[11],
                *m2 = (const float*)d_in[12], *v2 = (const float*)d_in[13];
    const float *W3 = (const float*)d_in[14], *b3 = (const float*)d_in[15],
                *g3 = (const float*)d_in[16], *be3= (const float*)d_in[17],
                *m3 = (const float*)d_in[18], *v3 = (const float*)d_in[19];
    const float *W4 = (const float*)d_in[20], *b4 = (const float*)d_in[21],
                *g4 = (const float*)d_in[22], *be4= (const float*)d_in[23],
                *m4 = (const float*)d_in[24], *v4 = (const float*)d_in[25];

    cudaFuncSetAttribute(mm_kernel<0>, cudaFuncAttributeMaxDynamicSharedMemorySize, MM_SMEM);
    cudaFuncSetAttribute(mm_kernel<1>, cudaFuncAttributeMaxDynamicSharedMemorySize, MM_SMEM);
    cudaFuncSetAttribute(mm_kernel<2>, cudaFuncAttributeMaxDynamicSharedMemorySize, MM_SMEM);

    setup_kernel<<<512, 256>>>(npts,
        W1, b1, g1, be1, m1, v1,  W2, b2, g2, be2, m2, v2,
        W3, b3, g3, be3, m3, v3,  W4, b4, g4, be4, m4, v4);
    h_kernel<<<NPTS / 8, 256>>>(x);

    mm_kernel<0><<<dim3(2, NPTS / 256), 256, MM_SMEM>>>();   // f = W2 h   (+ g segmax)
    fin_g_kernel<<<16, 256>>>();
    k_u_kernel<<<1024, 256>>>(W3, g3, v3);
    mm_kernel<1><<<dim3(4, NPTS / 256), 256, MM_SMEM>>>();   // h3 = relu(W3 f + u)
    mm_kernel<2><<<dim3(8, NPTS / 256), 256, MM_SMEM>>>();   // v = segmax(W4 h3)
    fin_v_kernel<<<64, 256>>>((float*)d_out);
}

// round 9
// speedup vs baseline: 5.1944x; 1.0874x over previous
#include <cuda_runtime.h>
#include <cuda_fp16.h>
#include <cstdint>

#define NPTS 131072
#define BSEG 16
#define EPSF 1e-5f

// ================= device scratch (allocation-free) =================
// activations: single fp16, point-major [pt][k]
__device__ __half d_a1[(size_t)NPTS * 128];
__device__ __half d_a2[(size_t)NPTS * 256];
__device__ __half d_a3[(size_t)NPTS * 512];
// BN-folded weights [Cout][Cin], single fp16
__device__ __half d_w2[256 * 128];
__device__ __half d_w3[512 * 256];
__device__ __half d_w4[1024 * 512];
__device__ float d_W1c[128 * 4];            // [c][w0,w1,w2,bias]
__device__ float d_b2f[256], d_b3f[512], d_b4f[1024];
__device__ float d_u[512 * BSEG];           // per-segment bias for layer3
__device__ unsigned d_gkey[BSEG * 256];
__device__ unsigned d_vkey[BSEG * 1024];
__device__ int d_seg[NPTS];

// ================= helpers =================
__device__ __forceinline__ unsigned f2key(float f) {
    unsigned u = __float_as_uint(f);
    return (u & 0x80000000u) ? ~u : (u | 0x80000000u);
}
__device__ __forceinline__ float key2f(unsigned k) {
    return (k & 0x80000000u) ? __uint_as_float(k & 0x7FFFFFFFu)
                             : __uint_as_float(~k);
}
__device__ __forceinline__ uint32_t smem_to_u32(const void* p) {
    uint32_t a;
    asm("{ .reg .u64 t; cvta.to.shared.u64 t, %1; cvt.u32.u64 %0, t; }" : "=r"(a) : "l"(p));
    return a;
}

// ---- baseline-PTX tensor ops ----
__device__ __forceinline__ void ldsm4(uint32_t (&r)[4], uint32_t addr) {
    asm volatile("ldmatrix.sync.aligned.m8n8.x4.shared.b16 {%0,%1,%2,%3}, [%4];"
                 : "=r"(r[0]), "=r"(r[1]), "=r"(r[2]), "=r"(r[3]) : "r"(addr));
}
__device__ __forceinline__ void mma16816(float (&d)[4], const uint32_t (&a)[4],
                                         uint32_t b0, uint32_t b1) {
    asm volatile("mma.sync.aligned.m16n8k16.row.col.f32.f16.f16.f32 "
                 "{%0,%1,%2,%3}, {%4,%5,%6,%7}, {%8,%9}, {%0,%1,%2,%3};"
                 : "+f"(d[0]), "+f"(d[1]), "+f"(d[2]), "+f"(d[3])
                 : "r"(a[0]), "r"(a[1]), "r"(a[2]), "r"(a[3]), "r"(b0), "r"(b1));
}
__device__ __forceinline__ void cpasync16(uint32_t saddr, const void* g) {
    asm volatile("cp.async.cg.shared.global [%0], [%1], 16;" :: "r"(saddr), "l"(g));
}
#define CP_COMMIT() asm volatile("cp.async.commit_group;" ::: "memory")
#define CP_WAIT(N)  asm volatile("cp.async.wait_group %0;" :: "n"(N) : "memory")

// ================= setup =================
__device__ __forceinline__ void fold_single(int t0, int stride,
        const float* __restrict__ W, const float* __restrict__ g, const float* __restrict__ v,
        __half* wd, int C, int Kdst, int Ksrc, int Koff) {
    for (int idx = t0; idx < C * Kdst; idx += stride) {
        int c = idx / Kdst, k = idx - c * Kdst;
        float s = g[c] * rsqrtf(v[c] + EPSF);
        wd[idx] = __float2half_rn(s * W[(size_t)c * Ksrc + Koff + k]);
    }
}
__device__ __forceinline__ void fold_bias(int t0, int stride,
        const float* b, const float* g, const float* be, const float* m, const float* v,
        float* bf, int C) {
    for (int i = t0; i < C; i += stride) {
        float s = g[i] * rsqrtf(v[i] + EPSF);
        bf[i] = s * b[i] + be[i] - s * m[i];
    }
}

__global__ void setup_kernel(const int* __restrict__ npts,
    const float* W1, const float* b1, const float* g1, const float* be1, const float* m1, const float* v1,
    const float* W2, const float* b2, const float* g2, const float* be2, const float* m2, const float* v2,
    const float* W3, const float* b3, const float* g3, const float* be3, const float* m3, const float* v3,
    const float* W4, const float* b4, const float* g4, const float* be4, const float* m4, const float* v4) {
    const int stride = gridDim.x * blockDim.x;
    const int t0 = blockIdx.x * blockDim.x + threadIdx.x;

    for (int c = t0; c < 128; c += stride) {
        float s = g1[c] * rsqrtf(v1[c] + EPSF);
        d_W1c[c * 4 + 0] = s * W1[c * 3 + 0];
        d_W1c[c * 4 + 1] = s * W1[c * 3 + 1];
        d_W1c[c * 4 + 2] = s * W1[c * 3 + 2];
        d_W1c[c * 4 + 3] = s * b1[c] + be1[c] - s * m1[c];
    }
    fold_single(t0, stride, W2, g2, v2, d_w2, 256,  128, 128, 0);
    fold_single(t0, stride, W3, g3, v3, d_w3, 512,  256, 512, 256);
    fold_single(t0, stride, W4, g4, v4, d_w4, 1024, 512, 512, 0);
    fold_bias(t0, stride, b2, g2, be2, m2, v2, d_b2f, 256);
    fold_bias(t0, stride, b3, g3, be3, m3, v3, d_b3f, 512);
    fold_bias(t0, stride, b4, g4, be4, m4, v4, d_b4f, 1024);

    int cum[BSEG];
    {
        int a = 0;
        #pragma unroll
        for (int t = 0; t < BSEG; t++) { a += __ldg(&npts[t]); cum[t] = a; }
    }
    for (int j = t0; j < NPTS; j += stride) {
        int s = 0;
        #pragma unroll
        for (int t = 0; t < BSEG - 1; t++) s += (j >= cum[t]);
        d_seg[j] = s;
    }
    for (int i = t0; i < BSEG * 1024; i += stride) d_vkey[i] = 0u;
    for (int i = t0; i < BSEG * 256;  i += stride) d_gkey[i] = 0u;
}

// layer1: one warp per point; lane handles 4 channels
__global__ void h_kernel(const float* __restrict__ x) {
    int pt   = blockIdx.x * 8 + (threadIdx.x >> 5);
    int lane = threadIdx.x & 31;
    float x0 = x[pt], x1 = x[NPTS + pt], x2 = x[2 * NPTS + pt];
    int c0 = lane * 4;
    uint32_t pk[2];
    #pragma unroll
    for (int p = 0; p < 2; p++) {
        __half2 hh;
        #pragma unroll
        for (int q = 0; q < 2; q++) {
            int c = c0 + p * 2 + q;
            const float* w = &d_W1c[c * 4];
            float v = fmaxf(w[3] + w[0] * x0 + w[1] * x1 + w[2] * x2, 0.0f);
            if (q == 0) hh.x = __float2half_rn(v); else hh.y = __float2half_rn(v);
        }
        pk[p] = *reinterpret_cast<uint32_t*>(&hh);
    }
    *reinterpret_cast<uint2*>(&d_a1[(size_t)pt * 128 + c0]) = make_uint2(pk[0], pk[1]);
}

__global__ void fin_v_kernel(float* __restrict__ out) {
    int i = blockIdx.x * blockDim.x + threadIdx.x;
    if (i < BSEG * 1024) out[i] = key2f(d_vkey[i]);
}
// one warp per (m, s) dot of length 256; reads g directly from gkey
__global__ void k_u_kernel(const float* __restrict__ W3,
                           const float* __restrict__ g3,
                           const float* __restrict__ v3) {
    int w = (blockIdx.x * blockDim.x + threadIdx.x) >> 5;
    int lane = threadIdx.x & 31;
    if (w >= 512 * BSEG) return;
    int m = w >> 4, s = w & 15;
    float acc = 0.0f;
    for (int r = lane; r < 256; r += 32)
        acc += W3[(size_t)m * 512 + r] * key2f(d_gkey[s * 256 + r]);
    #pragma unroll
    for (int o = 16; o; o >>= 1) acc += __shfl_xor_sync(0xffffffffu, acc, o);
    if (lane == 0) d_u[m * BSEG + s] = g3[m] * rsqrtf(v3[m] + EPSF) * acc;
}

// ================= mma.sync GEMM (fp16 x fp16, 64x64 warp tiles, K-chunk 64) =================
// CTA: 256 pts x 128 chans; 8 warps 4(m) x 2(n); per-warp 64x64.
// K chunks of 64; 3 stages; per chunk: A(256x64) + B(128x64). 144B-padded rows.
#define ROWB    144                   // 128 B data + 16 B pad (stride 9 mod 8 = 1: conflict-free)
#define ATILE   (256 * ROWB)          // 36864
#define BTILE   (128 * ROWB)          // 18432
#define STAGEB  (ATILE + BTILE)       // 55296
#define NSTAGE  3
#define RED_OFF (NSTAGE * STAGEB)     // float red[8][64]
#define MM_SMEM (RED_OFF + 2048)      // 167936 B

template<int CFG>
__global__ void __launch_bounds__(256, 1) mm_kernel() {
    constexpr int K    = (CFG == 0) ? 128 : (CFG == 1) ? 256 : 512;
    constexpr int MOUT = (CFG == 0) ? 256 : (CFG == 1) ? 512 : 1024;
    constexpr int KC   = K / 64;
    constexpr bool SEGMAX = (CFG != 1);
    constexpr bool STORE  = (CFG != 2);

    const __half* __restrict__ Ain = (CFG == 0) ? d_a1 : (CFG == 1) ? d_a2 : d_a3;
    const __half* __restrict__ Bw  = (CFG == 0) ? d_w2 : (CFG == 1) ? d_w3 : d_w4;
    const float* __restrict__ bias = (CFG == 0) ? d_b2f : (CFG == 1) ? d_b3f : d_b4f;
    __half* Oa = (CFG == 0) ? d_a2 : d_a3;
    unsigned* key = (CFG == 0) ? d_gkey : d_vkey;

    extern __shared__ char smem[];
    const uint32_t sb = smem_to_u32(smem);
    const int tid = threadIdx.x, wid = tid >> 5, lane = tid & 31;
    const int wm = wid & 3, wn = wid >> 2;
    const int n0 = blockIdx.x * 128;
    const int pt0 = blockIdx.y * 256;

    float acc[4][8][4];
    #pragma unroll
    for (int mi = 0; mi < 4; mi++)
        #pragma unroll
        for (int nt = 0; nt < 8; nt++)
            #pragma unroll
            for (int q = 0; q < 4; q++) acc[mi][nt][q] = 0.0f;

    auto load_chunk = [&](int kc, int buf) {
        const int k0 = kc * 64;
        const uint32_t base = sb + (uint32_t)buf * STAGEB;
        #pragma unroll
        for (int i = 0; i < 8; i++) {                  // A: 256 rows x 8 chunks
            int idx = i * 256 + tid;
            int row = idx >> 3, c8 = idx & 7;
            cpasync16(base + row * ROWB + c8 * 16,
                      Ain + (size_t)(pt0 + row) * K + k0 + c8 * 8);
        }
        #pragma unroll
        for (int i = 0; i < 4; i++) {                  // B: 128 rows x 8 chunks
            int idx = i * 256 + tid;
            int row = idx >> 3, c8 = idx & 7;
            cpasync16(base + ATILE + row * ROWB + c8 * 16,
                      Bw + (size_t)(n0 + row) * K + k0 + c8 * 8);
        }
        CP_COMMIT();
    };

    auto compute = [&](int buf) {
        const uint32_t ab = sb + (uint32_t)buf * STAGEB;
        const uint32_t bbB = ab + ATILE;
        #pragma unroll
        for (int kk = 0; kk < 4; kk++) {
            const uint32_t col = (uint32_t)((lane >> 4) * 16 + kk * 32);  // bytes
            uint32_t a_f[4][4];
            #pragma unroll
            for (int mi = 0; mi < 4; mi++) {
                uint32_t row = (uint32_t)(wm * 64 + mi * 16 + (lane & 15));
                ldsm4(a_f[mi], ab + row * ROWB + col);
            }
            #pragma unroll
            for (int nt4 = 0; nt4 < 4; nt4++) {
                uint32_t row = (uint32_t)(wn * 64 + nt4 * 16 + (lane & 15));
                uint32_t b_f[4];
                ldsm4(b_f, bbB + row * ROWB + col);
                #pragma unroll
                for (int mi = 0; mi < 4; mi++) {
                    mma16816(acc[mi][nt4 * 2 + 0], a_f[mi], b_f[0], b_f[2]);
                    mma16816(acc[mi][nt4 * 2 + 1], a_f[mi], b_f[1], b_f[3]);
                }
            }
        }
    };

    // 3-stage pipeline: one sync per chunk; final chunk fully drained (CP_WAIT(0))
    load_chunk(0, 0);
    if (KC > 1) load_chunk(1, 1);
    #pragma unroll 1
    for (int kc = 0; kc < KC; kc++) {
        if (kc + 1 < KC) { CP_WAIT(1); } else { CP_WAIT(0); }
        __syncthreads();
        if (kc + 2 < KC) load_chunk(kc + 2, (kc + 2) % NSTAGE);
        compute(kc % NSTAGE);
    }

    // ---- epilogue ----
    int ptr_[8], sg[8];
    #pragma unroll
    for (int mi = 0; mi < 4; mi++)
        #pragma unroll
        for (int h = 0; h < 2; h++) {
            int p = pt0 + wm * 64 + mi * 16 + (lane >> 2) + h * 8;
            ptr_[mi * 2 + h] = p;
            sg[mi * 2 + h] = d_seg[p];
        }
    const int cbase = n0 + wn * 64 + (lane & 3) * 2;

    #pragma unroll
    for (int mi = 0; mi < 4; mi++) {
        #pragma unroll
        for (int h = 0; h < 2; h++) {
            const int p = ptr_[mi * 2 + h];
            const int seg = sg[mi * 2 + h];
            #pragma unroll
            for (int nt = 0; nt < 8; nt++) {
                const int c = cbase + nt * 8;
                float v0 = acc[mi][nt][h * 2 + 0] + __ldg(&bias[c]);
                float v1 = acc[mi][nt][h * 2 + 1] + __ldg(&bias[c + 1]);
                if (CFG == 1) {
                    v0 = fmaxf(v0 + d_u[c * BSEG + seg], 0.0f);
                    v1 = fmaxf(v1 + d_u[(c + 1) * BSEG + seg], 0.0f);
                }
                acc[mi][nt][h * 2 + 0] = v0;
                acc[mi][nt][h * 2 + 1] = v1;
                if (STORE) {
                    __half2 hh;
                    hh.x = __float2half_rn(v0);
                    hh.y = __float2half_rn(v1);
                    *reinterpret_cast<uint32_t*>(&Oa[(size_t)p * MOUT + c]) =
                        *reinterpret_cast<uint32_t*>(&hh);
                }
            }
        }
    }

    if (SEGMAX) {
        float* red = reinterpret_cast<float*>(smem + RED_OFF);
        const int s_lo = d_seg[pt0], s_hi = d_seg[pt0 + 255];
        const int np = (s_lo == s_hi) ? 1 : 2;
        for (int pass = 0; pass < np; pass++) {
            const int s = pass ? s_hi : s_lo;
            float cm[8][2];
            #pragma unroll
            for (int nt = 0; nt < 8; nt++) { cm[nt][0] = -3.402823466e38f; cm[nt][1] = -3.402823466e38f; }
            #pragma unroll
            for (int mi = 0; mi < 4; mi++)
                #pragma unroll
                for (int h = 0; h < 2; h++)
                    if (sg[mi * 2 + h] == s) {
                        #pragma unroll
                        for (int nt = 0; nt < 8; nt++) {
                            cm[nt][0] = fmaxf(cm[nt][0], acc[mi][nt][h * 2 + 0]);
                            cm[nt][1] = fmaxf(cm[nt][1], acc[mi][nt][h * 2 + 1]);
                        }
                    }
            #pragma unroll
            for (int o = 4; o < 32; o <<= 1)
                #pragma unroll
                for (int nt = 0; nt < 8; nt++) {
                    cm[nt][0] = fmaxf(cm[nt][0], __shfl_xor_sync(0xffffffffu, cm[nt][0], o));
                    cm[nt][1] = fmaxf(cm[nt][1], __shfl_xor_sync(0xffffffffu, cm[nt][1], o));
                }
            __syncthreads();
            if ((lane >> 2) == 0) {
                #pragma unroll
                for (int nt = 0; nt < 8; nt++) {
                    red[wid * 64 + nt * 8 + (lane & 3) * 2 + 0] = cm[nt][0];
                    red[wid * 64 + nt * 8 + (lane & 3) * 2 + 1] = cm[nt][1];
                }
            }
            __syncthreads();
            if ((wid & 3) == 0) {
                const int wgrp = wid >> 2;
                #pragma unroll
                for (int cc = 0; cc < 2; cc++) {
                    const int col = lane * 2 + cc;
                    float m = red[(wgrp * 4 + 0) * 64 + col];
                    #pragma unroll
                    for (int w = 1; w < 4; w++)
                        m = fmaxf(m, red[(wgrp * 4 + w) * 64 + col]);
                    atomicMax(&key[s * MOUT + n0 + wgrp * 64 + col], f2key(m));
                }
            }
        }
    }
}

// ================= launch =================
extern "C" void kernel_launch(void* const* d_in, const int* in_sizes, int n_in,
                              void* d_out, int out_size) {
    const float* x    = (const float*)d_in[0];
    const int*   npts = (const int*  )d_in[1];
    const float *W1 = (const float*)d_in[2],  *b1 = (const float*)d_in[3],
                *g1 = (const float*)d_in[4],  *be1= (const float*)d_in[5],
                *m1 = (const float*)d_in[6],  *v1 = (const float*)d_in[7];
    const float *W2 = (const float*)d_in[8],  *b2 = (const float*)d_in[9],
                *g2 = (const float*)d_in[10], *be2= (const float*)d_in[11],
                *m2 = (const float*)d_in[12], *v2 = (const float*)d_in[13];
    const float *W3 = (const float*)d_in[14], *b3 = (const float*)d_in[15],
                *g3 = (const float*)d_in[16], *be3= (const float*)d_in[17],
                *m3 = (const float*)d_in[18], *v3 = (const float*)d_in[19];
    const float *W4 = (const float*)d_in[20], *b4 = (const float*)d_in[21],
                *g4 = (const float*)d_in[22], *be4= (const float*)d_in[23],
                *m4 = (const float*)d_in[24], *v4 = (const float*)d_in[25];

    cudaFuncSetAttribute(mm_kernel<0>, cudaFuncAttributeMaxDynamicSharedMemorySize, MM_SMEM);
    cudaFuncSetAttribute(mm_kernel<1>, cudaFuncAttributeMaxDynamicSharedMemorySize, MM_SMEM);
    cudaFuncSetAttribute(mm_kernel<2>, cudaFuncAttributeMaxDynamicSharedMemorySize, MM_SMEM);

    setup_kernel<<<512, 256>>>(npts,
        W1, b1, g1, be1, m1, v1,  W2, b2, g2, be2, m2, v2,
        W3, b3, g3, be3, m3, v3,  W4, b4, g4, be4, m4, v4);
    h_kernel<<<NPTS / 8, 256>>>(x);

    mm_kernel<0><<<dim3(2, NPTS / 256), 256, MM_SMEM>>>();   // f = W2 h   (+ g segmax)
    k_u_kernel<<<1024, 256>>>(W3, g3, v3);
    mm_kernel<1><<<dim3(4, NPTS / 256), 256, MM_SMEM>>>();   // h3 = relu(W3 f + u)
    mm_kernel<2><<<dim3(8, NPTS / 256), 256, MM_SMEM>>>();   // v = segmax(W4 h3)
    fin_v_kernel<<<64, 256>>>((float*)d_out);
}

// round 10
// speedup vs baseline: 6.0512x; 1.1650x over previous
#include <cuda_runtime.h>
#include <cuda_fp16.h>
#include <cstdint>

#define NPTS 131072
#define BSEG 16
#define EPSF 1e-5f

// ================= device scratch (allocation-free) =================
// activations: single fp16, point-major [pt][k]
__device__ __half d_a1[(size_t)NPTS * 128];
__device__ __half d_a2[(size_t)NPTS * 256];
__device__ __half d_a3[(size_t)NPTS * 512];
// BN-folded weights [Cout][Cin], single fp16
__device__ __half d_w2[256 * 128];
__device__ __half d_w3[512 * 256];
__device__ __half d_w4[1024 * 512];
__device__ float d_W1c[128 * 4];            // [c][w0,w1,w2,bias]
__device__ float d_b2f[256], d_b3f[512], d_b4f[1024];
__device__ float d_u[512 * BSEG];           // per-segment bias for layer3
__device__ unsigned d_gkey[BSEG * 256];
__device__ unsigned d_vkey[BSEG * 1024];
__device__ int d_seg[NPTS];

// ================= helpers =================
__device__ __forceinline__ unsigned f2key(float f) {
    unsigned u = __float_as_uint(f);
    return (u & 0x80000000u) ? ~u : (u | 0x80000000u);
}
__device__ __forceinline__ float key2f(unsigned k) {
    return (k & 0x80000000u) ? __uint_as_float(k & 0x7FFFFFFFu)
                             : __uint_as_float(~k);
}
__device__ __forceinline__ uint32_t smem_to_u32(const void* p) {
    uint32_t a;
    asm("{ .reg .u64 t; cvta.to.shared.u64 t, %1; cvt.u32.u64 %0, t; }" : "=r"(a) : "l"(p));
    return a;
}
// XOR swizzle for 128B rows: bits[7:9] -> bits[4:6] (conflict-free LDSM + STS.128)
#define SW128(o) ((o) ^ (((o) >> 3) & 0x70))

// ---- baseline-PTX tensor ops ----
__device__ __forceinline__ void ldsm4(uint32_t (&r)[4], uint32_t addr) {
    asm volatile("ldmatrix.sync.aligned.m8n8.x4.shared.b16 {%0,%1,%2,%3}, [%4];"
                 : "=r"(r[0]), "=r"(r[1]), "=r"(r[2]), "=r"(r[3]) : "r"(addr));
}
__device__ __forceinline__ void mma16816(float (&d)[4], const uint32_t (&a)[4],
                                         uint32_t b0, uint32_t b1) {
    asm volatile("mma.sync.aligned.m16n8k16.row.col.f32.f16.f16.f32 "
                 "{%0,%1,%2,%3}, {%4,%5,%6,%7}, {%8,%9}, {%0,%1,%2,%3};"
                 : "+f"(d[0]), "+f"(d[1]), "+f"(d[2]), "+f"(d[3])
                 : "r"(a[0]), "r"(a[1]), "r"(a[2]), "r"(a[3]), "r"(b0), "r"(b1));
}
__device__ __forceinline__ void cpasync16(uint32_t saddr, const void* g) {
    asm volatile("cp.async.cg.shared.global [%0], [%1], 16;" :: "r"(saddr), "l"(g));
}
#define CP_COMMIT() asm volatile("cp.async.commit_group;" ::: "memory")
#define CP_WAIT(N)  asm volatile("cp.async.wait_group %0;" :: "n"(N) : "memory")

// ================= setup =================
__device__ __forceinline__ void fold_single(int t0, int stride,
        const float* __restrict__ W, const float* __restrict__ g, const float* __restrict__ v,
        __half* wd, int C, int Kdst, int Ksrc, int Koff) {
    for (int idx = t0; idx < C * Kdst; idx += stride) {
        int c = idx / Kdst, k = idx - c * Kdst;
        float s = g[c] * rsqrtf(v[c] + EPSF);
        wd[idx] = __float2half_rn(s * W[(size_t)c * Ksrc + Koff + k]);
    }
}
__device__ __forceinline__ void fold_bias(int t0, int stride,
        const float* b, const float* g, const float* be, const float* m, const float* v,
        float* bf, int C) {
    for (int i = t0; i < C; i += stride) {
        float s = g[i] * rsqrtf(v[i] + EPSF);
        bf[i] = s * b[i] + be[i] - s * m[i];
    }
}

__global__ void setup_kernel(const int* __restrict__ npts,
    const float* W1, const float* b1, const float* g1, const float* be1, const float* m1, const float* v1,
    const float* W2, const float* b2, const float* g2, const float* be2, const float* m2, const float* v2,
    const float* W3, const float* b3, const float* g3, const float* be3, const float* m3, const float* v3,
    const float* W4, const float* b4, const float* g4, const float* be4, const float* m4, const float* v4) {
    const int stride = gridDim.x * blockDim.x;
    const int t0 = blockIdx.x * blockDim.x + threadIdx.x;

    for (int c = t0; c < 128; c += stride) {
        float s = g1[c] * rsqrtf(v1[c] + EPSF);
        d_W1c[c * 4 + 0] = s * W1[c * 3 + 0];
        d_W1c[c * 4 + 1] = s * W1[c * 3 + 1];
        d_W1c[c * 4 + 2] = s * W1[c * 3 + 2];
        d_W1c[c * 4 + 3] = s * b1[c] + be1[c] - s * m1[c];
    }
    fold_single(t0, stride, W2, g2, v2, d_w2, 256,  128, 128, 0);
    fold_single(t0, stride, W3, g3, v3, d_w3, 512,  256, 512, 256);
    fold_single(t0, stride, W4, g4, v4, d_w4, 1024, 512, 512, 0);
    fold_bias(t0, stride, b2, g2, be2, m2, v2, d_b2f, 256);
    fold_bias(t0, stride, b3, g3, be3, m3, v3, d_b3f, 512);
    fold_bias(t0, stride, b4, g4, be4, m4, v4, d_b4f, 1024);

    int cum[BSEG];
    {
        int a = 0;
        #pragma unroll
        for (int t = 0; t < BSEG; t++) { a += __ldg(&npts[t]); cum[t] = a; }
    }
    for (int j = t0; j < NPTS; j += stride) {
        int s = 0;
        #pragma unroll
        for (int t = 0; t < BSEG - 1; t++) s += (j >= cum[t]);
        d_seg[j] = s;
    }
    for (int i = t0; i < BSEG * 1024; i += stride) d_vkey[i] = 0u;
    for (int i = t0; i < BSEG * 256;  i += stride) d_gkey[i] = 0u;
}

// layer1: one warp per point; lane handles 4 channels
__global__ void h_kernel(const float* __restrict__ x) {
    int pt   = blockIdx.x * 8 + (threadIdx.x >> 5);
    int lane = threadIdx.x & 31;
    float x0 = x[pt], x1 = x[NPTS + pt], x2 = x[2 * NPTS + pt];
    int c0 = lane * 4;
    uint32_t pk[2];
    #pragma unroll
    for (int p = 0; p < 2; p++) {
        __half2 hh;
        #pragma unroll
        for (int q = 0; q < 2; q++) {
            int c = c0 + p * 2 + q;
            const float* w = &d_W1c[c * 4];
            float v = fmaxf(w[3] + w[0] * x0 + w[1] * x1 + w[2] * x2, 0.0f);
            if (q == 0) hh.x = __float2half_rn(v); else hh.y = __float2half_rn(v);
        }
        pk[p] = *reinterpret_cast<uint32_t*>(&hh);
    }
    *reinterpret_cast<uint2*>(&d_a1[(size_t)pt * 128 + c0]) = make_uint2(pk[0], pk[1]);
}

__global__ void fin_v_kernel(float* __restrict__ out) {
    int i = blockIdx.x * blockDim.x + threadIdx.x;
    if (i < BSEG * 1024) out[i] = key2f(d_vkey[i]);
}
// one warp per (m, s) dot of length 256; reads g directly from gkey
__global__ void k_u_kernel(const float* __restrict__ W3,
                           const float* __restrict__ g3,
                           const float* __restrict__ v3) {
    int w = (blockIdx.x * blockDim.x + threadIdx.x) >> 5;
    int lane = threadIdx.x & 31;
    if (w >= 512 * BSEG) return;
    int m = w >> 4, s = w & 15;
    float acc = 0.0f;
    for (int r = lane; r < 256; r += 32)
        acc += W3[(size_t)m * 512 + r] * key2f(d_gkey[s * 256 + r]);
    #pragma unroll
    for (int o = 16; o; o >>= 1) acc += __shfl_xor_sync(0xffffffffu, acc, o);
    if (lane == 0) d_u[m * BSEG + s] = g3[m] * rsqrtf(v3[m] + EPSF) * acc;
}

// ================= mma.sync GEMM (fp16 x fp16, 64x64 warp tiles, 2 CTAs/SM) =================
// CTA: 128 pts x 128 chans; 4 warps 2(m) x 2(n); per-warp 64x64.
// K chunks of 64; 3 stages; swizzled 128B rows (no pad). 97 KB smem/CTA -> 2 CTAs/SM.
#define ROWB    128
#define ATILE   (128 * ROWB)          // 16384
#define BTILE   (128 * ROWB)          // 16384
#define STAGEB  (ATILE + BTILE)       // 32768
#define NSTAGE  3
#define RED_OFF (NSTAGE * STAGEB)     // float red[4][64]
#define MM_SMEM (RED_OFF + 1024)      // 99328 B

template<int CFG>
__global__ void __launch_bounds__(128, 2) mm_kernel() {
    constexpr int K    = (CFG == 0) ? 128 : (CFG == 1) ? 256 : 512;
    constexpr int MOUT = (CFG == 0) ? 256 : (CFG == 1) ? 512 : 1024;
    constexpr int KC   = K / 64;
    constexpr bool SEGMAX = (CFG != 1);
    constexpr bool STORE  = (CFG != 2);

    const __half* __restrict__ Ain = (CFG == 0) ? d_a1 : (CFG == 1) ? d_a2 : d_a3;
    const __half* __restrict__ Bw  = (CFG == 0) ? d_w2 : (CFG == 1) ? d_w3 : d_w4;
    const float* __restrict__ bias = (CFG == 0) ? d_b2f : (CFG == 1) ? d_b3f : d_b4f;
    __half* Oa = (CFG == 0) ? d_a2 : d_a3;
    unsigned* key = (CFG == 0) ? d_gkey : d_vkey;

    extern __shared__ char smem[];
    const uint32_t sb = smem_to_u32(smem);
    const int tid = threadIdx.x, wid = tid >> 5, lane = tid & 31;
    const int wm = wid & 1, wn = wid >> 1;
    const int n0 = blockIdx.x * 128;
    const int pt0 = blockIdx.y * 128;

    float acc[4][8][4];
    #pragma unroll
    for (int mi = 0; mi < 4; mi++)
        #pragma unroll
        for (int nt = 0; nt < 8; nt++)
            #pragma unroll
            for (int q = 0; q < 4; q++) acc[mi][nt][q] = 0.0f;

    auto load_chunk = [&](int kc, int buf) {
        const int k0 = kc * 64;
        const uint32_t base = sb + (uint32_t)buf * STAGEB;
        #pragma unroll
        for (int i = 0; i < 8; i++) {                  // A: 128 rows x 8 16B-chunks
            int idx = i * 128 + tid;
            int row = idx >> 3, c8 = idx & 7;
            cpasync16(base + SW128((uint32_t)(row * ROWB + c8 * 16)),
                      Ain + (size_t)(pt0 + row) * K + k0 + c8 * 8);
        }
        #pragma unroll
        for (int i = 0; i < 8; i++) {                  // B: 128 rows x 8 16B-chunks
            int idx = i * 128 + tid;
            int row = idx >> 3, c8 = idx & 7;
            cpasync16(base + ATILE + SW128((uint32_t)(row * ROWB + c8 * 16)),
                      Bw + (size_t)(n0 + row) * K + k0 + c8 * 8);
        }
        CP_COMMIT();
    };

    auto compute = [&](int buf) {
        const uint32_t ab = sb + (uint32_t)buf * STAGEB;
        const uint32_t bbB = ab + ATILE;
        #pragma unroll
        for (int kk = 0; kk < 4; kk++) {
            const uint32_t col = (uint32_t)((lane >> 4) * 16 + kk * 32);  // bytes
            uint32_t a_f[4][4];
            #pragma unroll
            for (int mi = 0; mi < 4; mi++) {
                uint32_t row = (uint32_t)(wm * 64 + mi * 16 + (lane & 15));
                ldsm4(a_f[mi], ab + SW128(row * ROWB + col));
            }
            #pragma unroll
            for (int nt4 = 0; nt4 < 4; nt4++) {
                uint32_t row = (uint32_t)(wn * 64 + nt4 * 16 + (lane & 15));
                uint32_t b_f[4];
                ldsm4(b_f, bbB + SW128(row * ROWB + col));
                #pragma unroll
                for (int mi = 0; mi < 4; mi++) {
                    mma16816(acc[mi][nt4 * 2 + 0], a_f[mi], b_f[0], b_f[2]);
                    mma16816(acc[mi][nt4 * 2 + 1], a_f[mi], b_f[1], b_f[3]);
                }
            }
        }
    };

    // 3-stage pipeline: one sync per chunk; final chunk fully drained
    load_chunk(0, 0);
    if (KC > 1) load_chunk(1, 1);
    #pragma unroll 1
    for (int kc = 0; kc < KC; kc++) {
        if (kc + 1 < KC) { CP_WAIT(1); } else { CP_WAIT(0); }
        __syncthreads();
        if (kc + 2 < KC) load_chunk(kc + 2, (kc + 2) % NSTAGE);
        compute(kc % NSTAGE);
    }

    // ---- epilogue ----
    int ptr_[8], sg[8];
    #pragma unroll
    for (int mi = 0; mi < 4; mi++)
        #pragma unroll
        for (int h = 0; h < 2; h++) {
            int p = pt0 + wm * 64 + mi * 16 + (lane >> 2) + h * 8;
            ptr_[mi * 2 + h] = p;
            sg[mi * 2 + h] = d_seg[p];
        }
    const int cbase = n0 + wn * 64 + (lane & 3) * 2;

    #pragma unroll
    for (int mi = 0; mi < 4; mi++) {
        #pragma unroll
        for (int h = 0; h < 2; h++) {
            const int p = ptr_[mi * 2 + h];
            const int seg = sg[mi * 2 + h];
            #pragma unroll
            for (int nt = 0; nt < 8; nt++) {
                const int c = cbase + nt * 8;
                float v0 = acc[mi][nt][h * 2 + 0] + __ldg(&bias[c]);
                float v1 = acc[mi][nt][h * 2 + 1] + __ldg(&bias[c + 1]);
                if (CFG == 1) {
                    v0 = fmaxf(v0 + d_u[c * BSEG + seg], 0.0f);
                    v1 = fmaxf(v1 + d_u[(c + 1) * BSEG + seg], 0.0f);
                }
                acc[mi][nt][h * 2 + 0] = v0;
                acc[mi][nt][h * 2 + 1] = v1;
                if (STORE) {
                    __half2 hh;
                    hh.x = __float2half_rn(v0);
                    hh.y = __float2half_rn(v1);
                    *reinterpret_cast<uint32_t*>(&Oa[(size_t)p * MOUT + c]) =
                        *reinterpret_cast<uint32_t*>(&hh);
                }
            }
        }
    }

    if (SEGMAX) {
        float* red = reinterpret_cast<float*>(smem + RED_OFF);
        const int s_lo = d_seg[pt0], s_hi = d_seg[pt0 + 127];
        const int np = (s_lo == s_hi) ? 1 : 2;
        for (int pass = 0; pass < np; pass++) {
            const int s = pass ? s_hi : s_lo;
            float cm[8][2];
            #pragma unroll
            for (int nt = 0; nt < 8; nt++) { cm[nt][0] = -3.402823466e38f; cm[nt][1] = -3.402823466e38f; }
            #pragma unroll
            for (int mi = 0; mi < 4; mi++)
                #pragma unroll
                for (int h = 0; h < 2; h++)
                    if (sg[mi * 2 + h] == s) {
                        #pragma unroll
                        for (int nt = 0; nt < 8; nt++) {
                            cm[nt][0] = fmaxf(cm[nt][0], acc[mi][nt][h * 2 + 0]);
                            cm[nt][1] = fmaxf(cm[nt][1], acc[mi][nt][h * 2 + 1]);
                        }
                    }
            #pragma unroll
            for (int o = 4; o < 32; o <<= 1)
                #pragma unroll
                for (int nt = 0; nt < 8; nt++) {
                    cm[nt][0] = fmaxf(cm[nt][0], __shfl_xor_sync(0xffffffffu, cm[nt][0], o));
                    cm[nt][1] = fmaxf(cm[nt][1], __shfl_xor_sync(0xffffffffu, cm[nt][1], o));
                }
            __syncthreads();
            if ((lane >> 2) == 0) {
                #pragma unroll
                for (int nt = 0; nt < 8; nt++) {
                    red[wid * 64 + nt * 8 + (lane & 3) * 2 + 0] = cm[nt][0];
                    red[wid * 64 + nt * 8 + (lane & 3) * 2 + 1] = cm[nt][1];
                }
            }
            __syncthreads();
            if ((wid & 1) == 0) {   // wid 0 (wn=0), wid 2 (wn=1)
                const int wgrp = wid >> 1;
                #pragma unroll
                for (int cc = 0; cc < 2; cc++) {
                    const int col = lane * 2 + cc;
                    float m = fmaxf(red[(wgrp * 2 + 0) * 64 + col],
                                    red[(wgrp * 2 + 1) * 64 + col]);
                    atomicMax(&key[s * MOUT + n0 + wgrp * 64 + col], f2key(m));
                }
            }
        }
    }
}

// ================= launch =================
extern "C" void kernel_launch(void* const* d_in, const int* in_sizes, int n_in,
                              void* d_out, int out_size) {
    const float* x    = (const float*)d_in[0];
    const int*   npts = (const int*  )d_in[1];
    const float *W1 = (const float*)d_in[2],  *b1 = (const float*)d_in[3],
                *g1 = (const float*)d_in[4],  *be1= (const float*)d_in[5],
                *m1 = (const float*)d_in[6],  *v1 = (const float*)d_in[7];
    const float *W2 = (const float*)d_in[8],  *b2 = (const float*)d_in[9],
                *g2 = (const float*)d_in[10], *be2= (const float*)d_in[11],
                *m2 = (const float*)d_in[12], *v2 = (const float*)d_in[13];
    const float *W3 = (const float*)d_in[14], *b3 = (const float*)d_in[15],
                *g3 = (const float*)d_in[16], *be3= (const float*)d_in[17],
                *m3 = (const float*)d_in[18], *v3 = (const float*)d_in[19];
    const float *W4 = (const float*)d_in[20], *b4 = (const float*)d_in[21],
                *g4 = (const float*)d_in[22], *be4= (const float*)d_in[23],
                *m4 = (const float*)d_in[24], *v4 = (const float*)d_in[25];

    cudaFuncSetAttribute(mm_kernel<0>, cudaFuncAttributeMaxDynamicSharedMemorySize, MM_SMEM);
    cudaFuncSetAttribute(mm_kernel<1>, cudaFuncAttributeMaxDynamicSharedMemorySize, MM_SMEM);
    cudaFuncSetAttribute(mm_kernel<2>, cudaFuncAttributeMaxDynamicSharedMemorySize, MM_SMEM);

    setup_kernel<<<512, 256>>>(npts,
        W1, b1, g1, be1, m1, v1,  W2, b2, g2, be2, m2, v2,
        W3, b3, g3, be3, m3, v3,  W4, b4, g4, be4, m4, v4);
    h_kernel<<<NPTS / 8, 256>>>(x);

    mm_kernel<0><<<dim3(2, NPTS / 128), 128, MM_SMEM>>>();   // f = W2 h   (+ g segmax)
    k_u_kernel<<<1024, 256>>>(W3, g3, v3);
    mm_kernel<1><<<dim3(4, NPTS / 128), 128, MM_SMEM>>>();   // h3 = relu(W3 f + u)
    mm_kernel<2><<<dim3(8, NPTS / 128), 128, MM_SMEM>>>();   // v = segmax(W4 h3)
    fin_v_kernel<<<64, 256>>>((float*)d_out);
}

// round 11
// speedup vs baseline: 7.1213x; 1.1768x over previous
#include <cuda_runtime.h>
#include <cuda_fp16.h>
#include <cstdint>

#define NPTS 131072
#define BSEG 16
#define EPSF 1e-5f

// ================= device scratch (allocation-free) =================
// activations: single fp16, point-major [pt][k]  (a1 is fused into mm0 now)
__device__ __half d_a2[(size_t)NPTS * 256];
__device__ __half d_a3[(size_t)NPTS * 512];
// BN-folded weights [Cout][Cin], single fp16
__device__ __half d_w2[256 * 128];
__device__ __half d_w3[512 * 256];
__device__ __half d_w4[1024 * 512];
__device__ float d_W1c[128 * 4];            // [c][w0,w1,w2,bias]
__device__ float d_b2f[256], d_b3f[512], d_b4f[1024];
__device__ float d_u[512 * BSEG];           // per-segment bias for layer3
__device__ unsigned d_gkey[BSEG * 256];
__device__ unsigned d_vkey[BSEG * 1024];
__device__ int d_seg[NPTS];

// ================= helpers =================
__device__ __forceinline__ unsigned f2key(float f) {
    unsigned u = __float_as_uint(f);
    return (u & 0x80000000u) ? ~u : (u | 0x80000000u);
}
__device__ __forceinline__ float key2f(unsigned k) {
    return (k & 0x80000000u) ? __uint_as_float(k & 0x7FFFFFFFu)
                             : __uint_as_float(~k);
}
__device__ __forceinline__ uint32_t smem_to_u32(const void* p) {
    uint32_t a;
    asm("{ .reg .u64 t; cvta.to.shared.u64 t, %1; cvt.u32.u64 %0, t; }" : "=r"(a) : "l"(p));
    return a;
}
// XOR swizzle for 128B rows: bits[7:9] -> bits[4:6] (conflict-free LDSM + STS.128)
#define SW128(o) ((o) ^ (((o) >> 3) & 0x70))

// ---- baseline-PTX tensor ops ----
__device__ __forceinline__ void ldsm4(uint32_t (&r)[4], uint32_t addr) {
    asm volatile("ldmatrix.sync.aligned.m8n8.x4.shared.b16 {%0,%1,%2,%3}, [%4];"
                 : "=r"(r[0]), "=r"(r[1]), "=r"(r[2]), "=r"(r[3]) : "r"(addr));
}
__device__ __forceinline__ void mma16816(float (&d)[4], const uint32_t (&a)[4],
                                         uint32_t b0, uint32_t b1) {
    asm volatile("mma.sync.aligned.m16n8k16.row.col.f32.f16.f16.f32 "
                 "{%0,%1,%2,%3}, {%4,%5,%6,%7}, {%8,%9}, {%0,%1,%2,%3};"
                 : "+f"(d[0]), "+f"(d[1]), "+f"(d[2]), "+f"(d[3])
                 : "r"(a[0]), "r"(a[1]), "r"(a[2]), "r"(a[3]), "r"(b0), "r"(b1));
}
__device__ __forceinline__ void cpasync16(uint32_t saddr, const void* g) {
    asm volatile("cp.async.cg.shared.global [%0], [%1], 16;" :: "r"(saddr), "l"(g));
}
#define CP_COMMIT() asm volatile("cp.async.commit_group;" ::: "memory")
#define CP_WAIT(N)  asm volatile("cp.async.wait_group %0;" :: "n"(N) : "memory")

// ================= setup =================
__device__ __forceinline__ void fold_single(int t0, int stride,
        const float* __restrict__ W, const float* __restrict__ g, const float* __restrict__ v,
        __half* wd, int C, int Kdst, int Ksrc, int Koff) {
    for (int idx = t0; idx < C * Kdst; idx += stride) {
        int c = idx / Kdst, k = idx - c * Kdst;
        float s = g[c] * rsqrtf(v[c] + EPSF);
        wd[idx] = __float2half_rn(s * W[(size_t)c * Ksrc + Koff + k]);
    }
}
__device__ __forceinline__ void fold_bias(int t0, int stride,
        const float* b, const float* g, const float* be, const float* m, const float* v,
        float* bf, int C) {
    for (int i = t0; i < C; i += stride) {
        float s = g[i] * rsqrtf(v[i] + EPSF);
        bf[i] = s * b[i] + be[i] - s * m[i];
    }
}

__global__ void setup_kernel(const int* __restrict__ npts,
    const float* W1, const float* b1, const float* g1, const float* be1, const float* m1, const float* v1,
    const float* W2, const float* b2, const float* g2, const float* be2, const float* m2, const float* v2,
    const float* W3, const float* b3, const float* g3, const float* be3, const float* m3, const float* v3,
    const float* W4, const float* b4, const float* g4, const float* be4, const float* m4, const float* v4) {
    const int stride = gridDim.x * blockDim.x;
    const int t0 = blockIdx.x * blockDim.x + threadIdx.x;

    for (int c = t0; c < 128; c += stride) {
        float s = g1[c] * rsqrtf(v1[c] + EPSF);
        d_W1c[c * 4 + 0] = s * W1[c * 3 + 0];
        d_W1c[c * 4 + 1] = s * W1[c * 3 + 1];
        d_W1c[c * 4 + 2] = s * W1[c * 3 + 2];
        d_W1c[c * 4 + 3] = s * b1[c] + be1[c] - s * m1[c];
    }
    fold_single(t0, stride, W2, g2, v2, d_w2, 256,  128, 128, 0);
    fold_single(t0, stride, W3, g3, v3, d_w3, 512,  256, 512, 256);
    fold_single(t0, stride, W4, g4, v4, d_w4, 1024, 512, 512, 0);
    fold_bias(t0, stride, b2, g2, be2, m2, v2, d_b2f, 256);
    fold_bias(t0, stride, b3, g3, be3, m3, v3, d_b3f, 512);
    fold_bias(t0, stride, b4, g4, be4, m4, v4, d_b4f, 1024);

    int cum[BSEG];
    {
        int a = 0;
        #pragma unroll
        for (int t = 0; t < BSEG; t++) { a += __ldg(&npts[t]); cum[t] = a; }
    }
    for (int j = t0; j < NPTS; j += stride) {
        int s = 0;
        #pragma unroll
        for (int t = 0; t < BSEG - 1; t++) s += (j >= cum[t]);
        d_seg[j] = s;
    }
    for (int i = t0; i < BSEG * 1024; i += stride) d_vkey[i] = 0u;
    for (int i = t0; i < BSEG * 256;  i += stride) d_gkey[i] = 0u;
}

__global__ void fin_v_kernel(float* __restrict__ out) {
    int i = blockIdx.x * blockDim.x + threadIdx.x;
    if (i < BSEG * 1024) out[i] = key2f(d_vkey[i]);
}
// one warp per (m, s) dot of length 256; reads g directly from gkey
__global__ void k_u_kernel(const float* __restrict__ W3,
                           const float* __restrict__ g3,
                           const float* __restrict__ v3) {
    int w = (blockIdx.x * blockDim.x + threadIdx.x) >> 5;
    int lane = threadIdx.x & 31;
    if (w >= 512 * BSEG) return;
    int m = w >> 4, s = w & 15;
    float acc = 0.0f;
    for (int r = lane; r < 256; r += 32)
        acc += W3[(size_t)m * 512 + r] * key2f(d_gkey[s * 256 + r]);
    #pragma unroll
    for (int o = 16; o; o >>= 1) acc += __shfl_xor_sync(0xffffffffu, acc, o);
    if (lane == 0) d_u[m * BSEG + s] = g3[m] * rsqrtf(v3[m] + EPSF) * acc;
}

// ================= mma.sync GEMM (fp16 x fp16, 64x64 warp tiles, 2 CTAs/SM) =================
// CTA: 128 pts x 128 chans; 4 warps 2(m) x 2(n); per-warp 64x64.
// K chunks of 64; 3 stages; swizzled 128B rows. 97 KB smem/CTA -> 2 CTAs/SM.
// CFG0 fuses layer-1: A = relu(bn1(W1 x)) computed in-kernel (no d_a1).
#define ROWB    128
#define ATILE   (128 * ROWB)          // 16384
#define BTILE   (128 * ROWB)          // 16384
#define STAGEB  (ATILE + BTILE)       // 32768
#define NSTAGE  3
#define RED_OFF (NSTAGE * STAGEB)     // float red[4][64]
#define MM_SMEM (RED_OFF + 1024)      // 99328 B

template<int CFG>
__global__ void __launch_bounds__(128, 2) mm_kernel(const float* __restrict__ xg) {
    constexpr int K    = (CFG == 0) ? 128 : (CFG == 1) ? 256 : 512;
    constexpr int MOUT = (CFG == 0) ? 256 : (CFG == 1) ? 512 : 1024;
    constexpr int KC   = K / 64;
    constexpr bool SEGMAX = (CFG != 1);
    constexpr bool STORE  = (CFG != 2);
    constexpr bool FUSE1  = (CFG == 0);

    const __half* __restrict__ Ain = (CFG == 1) ? d_a2 : d_a3;   // unused for CFG0
    const __half* __restrict__ Bw  = (CFG == 0) ? d_w2 : (CFG == 1) ? d_w3 : d_w4;
    const float* __restrict__ bias = (CFG == 0) ? d_b2f : (CFG == 1) ? d_b3f : d_b4f;
    __half* Oa = (CFG == 0) ? d_a2 : d_a3;
    unsigned* key = (CFG == 0) ? d_gkey : d_vkey;

    extern __shared__ char smem[];
    const uint32_t sb = smem_to_u32(smem);
    const int tid = threadIdx.x, wid = tid >> 5, lane = tid & 31;
    const int wm = wid & 1, wn = wid >> 1;
    const int n0 = blockIdx.x * 128;
    const int pt0 = blockIdx.y * 128;

    float acc[4][8][4];
    #pragma unroll
    for (int mi = 0; mi < 4; mi++)
        #pragma unroll
        for (int nt = 0; nt < 8; nt++)
            #pragma unroll
            for (int q = 0; q < 4; q++) acc[mi][nt][q] = 0.0f;

    auto load_B = [&](int kc, int buf) {
        const int k0 = kc * 64;
        const uint32_t base = sb + (uint32_t)buf * STAGEB;
        #pragma unroll
        for (int i = 0; i < 8; i++) {
            int idx = i * 128 + tid;
            int row = idx >> 3, c8 = idx & 7;
            cpasync16(base + ATILE + SW128((uint32_t)(row * ROWB + c8 * 16)),
                      Bw + (size_t)(n0 + row) * K + k0 + c8 * 8);
        }
    };
    auto load_chunk = [&](int kc, int buf) {
        const int k0 = kc * 64;
        const uint32_t base = sb + (uint32_t)buf * STAGEB;
        #pragma unroll
        for (int i = 0; i < 8; i++) {
            int idx = i * 128 + tid;
            int row = idx >> 3, c8 = idx & 7;
            cpasync16(base + SW128((uint32_t)(row * ROWB + c8 * 16)),
                      Ain + (size_t)(pt0 + row) * K + k0 + c8 * 8);
        }
        load_B(kc, buf);
        CP_COMMIT();
    };

    auto compute = [&](int buf) {
        const uint32_t ab = sb + (uint32_t)buf * STAGEB;
        const uint32_t bbB = ab + ATILE;
        #pragma unroll
        for (int kk = 0; kk < 4; kk++) {
            const uint32_t col = (uint32_t)((lane >> 4) * 16 + kk * 32);  // bytes
            uint32_t a_f[4][4];
            #pragma unroll
            for (int mi = 0; mi < 4; mi++) {
                uint32_t row = (uint32_t)(wm * 64 + mi * 16 + (lane & 15));
                ldsm4(a_f[mi], ab + SW128(row * ROWB + col));
            }
            #pragma unroll
            for (int nt4 = 0; nt4 < 4; nt4++) {
                uint32_t row = (uint32_t)(wn * 64 + nt4 * 16 + (lane & 15));
                uint32_t b_f[4];
                ldsm4(b_f, bbB + SW128(row * ROWB + col));
                #pragma unroll
                for (int mi = 0; mi < 4; mi++) {
                    mma16816(acc[mi][nt4 * 2 + 0], a_f[mi], b_f[0], b_f[2]);
                    mma16816(acc[mi][nt4 * 2 + 1], a_f[mi], b_f[1], b_f[3]);
                }
            }
        }
    };

    if (FUSE1) {
        // B for both K-chunks in flight; A computed in-kernel meanwhile.
        load_B(0, 0); CP_COMMIT();
        load_B(1, 1); CP_COMMIT();
        // layer-1: thread -> one point, all 128 channels, into stage0/1 A-regions
        {
            const int pt = pt0 + tid;
            const float x0 = xg[pt], x1 = xg[NPTS + pt], x2 = xg[2 * NPTS + pt];
            #pragma unroll
            for (int g8 = 0; g8 < 16; g8++) {          // 16 groups of 8 channels
                __half2 h2[4];
                #pragma unroll
                for (int q = 0; q < 4; q++) {
                    #pragma unroll
                    for (int r = 0; r < 2; r++) {
                        const int c = g8 * 8 + q * 2 + r;
                        const float* w = &d_W1c[c * 4];
                        float v = fmaxf(__ldg(&w[3]) + __ldg(&w[0]) * x0
                                      + __ldg(&w[1]) * x1 + __ldg(&w[2]) * x2, 0.0f);
                        if (r == 0) h2[q].x = __float2half_rn(v);
                        else        h2[q].y = __float2half_rn(v);
                    }
                }
                const int chunk = g8 >> 3;             // K-chunk 0 or 1
                const int c8 = g8 & 7;                 // 16B unit within row
                uint32_t dst = sb + (uint32_t)chunk * STAGEB
                             + SW128((uint32_t)(tid * ROWB + c8 * 16));
                *reinterpret_cast<uint4*>(smem + (dst - sb)) =
                    *reinterpret_cast<uint4*>(h2);
            }
        }
    } else {
        load_chunk(0, 0);
        if (KC > 1) load_chunk(1, 1);
    }

    #pragma unroll 1
    for (int kc = 0; kc < KC; kc++) {
        if (kc + 1 < KC) { CP_WAIT(1); } else { CP_WAIT(0); }
        __syncthreads();
        if (!FUSE1 && kc + 2 < KC) load_chunk(kc + 2, (kc + 2) % NSTAGE);
        compute(FUSE1 ? kc : (kc % NSTAGE));
    }

    // ---- epilogue ----
    int ptr_[8], sg[8];
    #pragma unroll
    for (int mi = 0; mi < 4; mi++)
        #pragma unroll
        for (int h = 0; h < 2; h++) {
            int p = pt0 + wm * 64 + mi * 16 + (lane >> 2) + h * 8;
            ptr_[mi * 2 + h] = p;
            sg[mi * 2 + h] = d_seg[p];
        }
    const int cbase = n0 + wn * 64 + (lane & 3) * 2;

    #pragma unroll
    for (int mi = 0; mi < 4; mi++) {
        #pragma unroll
        for (int h = 0; h < 2; h++) {
            const int p = ptr_[mi * 2 + h];
            const int seg = sg[mi * 2 + h];
            #pragma unroll
            for (int nt = 0; nt < 8; nt++) {
                const int c = cbase + nt * 8;
                float v0 = acc[mi][nt][h * 2 + 0] + __ldg(&bias[c]);
                float v1 = acc[mi][nt][h * 2 + 1] + __ldg(&bias[c + 1]);
                if (CFG == 1) {
                    v0 = fmaxf(v0 + d_u[c * BSEG + seg], 0.0f);
                    v1 = fmaxf(v1 + d_u[(c + 1) * BSEG + seg], 0.0f);
                }
                acc[mi][nt][h * 2 + 0] = v0;
                acc[mi][nt][h * 2 + 1] = v1;
                if (STORE) {
                    __half2 hh;
                    hh.x = __float2half_rn(v0);
                    hh.y = __float2half_rn(v1);
                    *reinterpret_cast<uint32_t*>(&Oa[(size_t)p * MOUT + c]) =
                        *reinterpret_cast<uint32_t*>(&hh);
                }
            }
        }
    }

    if (SEGMAX) {
        float* red = reinterpret_cast<float*>(smem + RED_OFF);
        const int s_lo = d_seg[pt0], s_hi = d_seg[pt0 + 127];
        const int np = (s_lo == s_hi) ? 1 : 2;
        for (int pass = 0; pass < np; pass++) {
            const int s = pass ? s_hi : s_lo;
            float cm[8][2];
            #pragma unroll
            for (int nt = 0; nt < 8; nt++) { cm[nt][0] = -3.402823466e38f; cm[nt][1] = -3.402823466e38f; }
            #pragma unroll
            for (int mi = 0; mi < 4; mi++)
                #pragma unroll
                for (int h = 0; h < 2; h++)
                    if (sg[mi * 2 + h] == s) {
                        #pragma unroll
                        for (int nt = 0; nt < 8; nt++) {
                            cm[nt][0] = fmaxf(cm[nt][0], acc[mi][nt][h * 2 + 0]);
                            cm[nt][1] = fmaxf(cm[nt][1], acc[mi][nt][h * 2 + 1]);
                        }
                    }
            #pragma unroll
            for (int o = 4; o < 32; o <<= 1)
                #pragma unroll
                for (int nt = 0; nt < 8; nt++) {
                    cm[nt][0] = fmaxf(cm[nt][0], __shfl_xor_sync(0xffffffffu, cm[nt][0], o));
                    cm[nt][1] = fmaxf(cm[nt][1], __shfl_xor_sync(0xffffffffu, cm[nt][1], o));
                }
            __syncthreads();
            if ((lane >> 2) == 0) {
                #pragma unroll
                for (int nt = 0; nt < 8; nt++) {
                    red[wid * 64 + nt * 8 + (lane & 3) * 2 + 0] = cm[nt][0];
                    red[wid * 64 + nt * 8 + (lane & 3) * 2 + 1] = cm[nt][1];
                }
            }
            __syncthreads();
            if ((wid & 1) == 0) {   // wid 0 (wn=0), wid 2 (wn=1)
                const int wgrp = wid >> 1;
                #pragma unroll
                for (int cc = 0; cc < 2; cc++) {
                    const int col = lane * 2 + cc;
                    float m = fmaxf(red[(wgrp * 2 + 0) * 64 + col],
                                    red[(wgrp * 2 + 1) * 64 + col]);
                    atomicMax(&key[s * MOUT + n0 + wgrp * 64 + col], f2key(m));
                }
            }
        }
    }
}

// ================= launch =================
extern "C" void kernel_launch(void* const* d_in, const int* in_sizes, int n_in,
                              void* d_out, int out_size) {
    const float* x    = (const float*)d_in[0];
    const int*   npts = (const int*  )d_in[1];
    const float *W1 = (const float*)d_in[2],  *b1 = (const float*)d_in[3],
                *g1 = (const float*)d_in[4],  *be1= (const float*)d_in[5],
                *m1 = (const float*)d_in[6],  *v1 = (const float*)d_in[7];
    const float *W2 = (const float*)d_in[8],  *b2 = (const float*)d_in[9],
                *g2 = (const float*)d_in[10], *be2= (const float*)d_in[11],
                *m2 = (const float*)d_in[12], *v2 = (const float*)d_in[13];
    const float *W3 = (const float*)d_in[14], *b3 = (const float*)d_in[15],
                *g3 = (const float*)d_in[16], *be3= (const float*)d_in[17],
                *m3 = (const float*)d_in[18], *v3 = (const float*)d_in[19];
    const float *W4 = (const float*)d_in[20], *b4 = (const float*)d_in[21],
                *g4 = (const float*)d_in[22], *be4= (const float*)d_in[23],
                *m4 = (const float*)d_in[24], *v4 = (const float*)d_in[25];

    cudaFuncSetAttribute(mm_kernel<0>, cudaFuncAttributeMaxDynamicSharedMemorySize, MM_SMEM);
    cudaFuncSetAttribute(mm_kernel<1>, cudaFuncAttributeMaxDynamicSharedMemorySize, MM_SMEM);
    cudaFuncSetAttribute(mm_kernel<2>, cudaFuncAttributeMaxDynamicSharedMemorySize, MM_SMEM);

    setup_kernel<<<512, 256>>>(npts,
        W1, b1, g1, be1, m1, v1,  W2, b2, g2, be2, m2, v2,
        W3, b3, g3, be3, m3, v3,  W4, b4, g4, be4, m4, v4);

    mm_kernel<0><<<dim3(2, NPTS / 128), 128, MM_SMEM>>>(x);  // #2: f (+g segmax), layer1 fused
    k_u_kernel<<<1024, 256>>>(W3, g3, v3);                   // #3
    mm_kernel<1><<<dim3(4, NPTS / 128), 128, MM_SMEM>>>(x);  // #4: h3  <- ncu captures this
    mm_kernel<2><<<dim3(8, NPTS / 128), 128, MM_SMEM>>>(x);  // #5: v segmax
    fin_v_kernel<<<64, 256>>>((float*)d_out);                // #6
}

// round 12
// speedup vs baseline: 7.2924x; 1.0240x over previous
#include <cuda_runtime.h>
#include <cuda_fp16.h>
#include <cstdint>

#define NPTS 131072
#define BSEG 16
#define EPSF 1e-5f

// ================= device scratch (allocation-free) =================
__device__ __half d_a2[(size_t)NPTS * 256];
__device__ __half d_a3[(size_t)NPTS * 512];
__device__ __half d_w2[256 * 128];
__device__ __half d_w3[512 * 256];
__device__ __half d_w4[1024 * 512];
__device__ float d_W1c[128 * 4];            // [c][w0,w1,w2,bias]
__device__ float d_b2f[256], d_b3f[512], d_b4f[1024];
__device__ float d_u[512 * BSEG];           // per-segment bias for layer3
__device__ unsigned d_gkey[BSEG * 256];
__device__ unsigned d_vkey[BSEG * 1024];
__device__ int d_seg[NPTS];

// ================= helpers =================
__device__ __forceinline__ unsigned f2key(float f) {
    unsigned u = __float_as_uint(f);
    return (u & 0x80000000u) ? ~u : (u | 0x80000000u);
}
__device__ __forceinline__ float key2f(unsigned k) {
    return (k & 0x80000000u) ? __uint_as_float(k & 0x7FFFFFFFu)
                             : __uint_as_float(~k);
}
__device__ __forceinline__ uint32_t smem_to_u32(const void* p) {
    uint32_t a;
    asm("{ .reg .u64 t; cvta.to.shared.u64 t, %1; cvt.u32.u64 %0, t; }" : "=r"(a) : "l"(p));
    return a;
}
#define SW128(o) ((o) ^ (((o) >> 3) & 0x70))

// ---- baseline-PTX tensor ops ----
__device__ __forceinline__ void ldsm4(uint32_t (&r)[4], uint32_t addr) {
    asm volatile("ldmatrix.sync.aligned.m8n8.x4.shared.b16 {%0,%1,%2,%3}, [%4];"
                 : "=r"(r[0]), "=r"(r[1]), "=r"(r[2]), "=r"(r[3]) : "r"(addr));
}
__device__ __forceinline__ void mma16816(float (&d)[4], const uint32_t (&a)[4],
                                         uint32_t b0, uint32_t b1) {
    asm volatile("mma.sync.aligned.m16n8k16.row.col.f32.f16.f16.f32 "
                 "{%0,%1,%2,%3}, {%4,%5,%6,%7}, {%8,%9}, {%0,%1,%2,%3};"
                 : "+f"(d[0]), "+f"(d[1]), "+f"(d[2]), "+f"(d[3])
                 : "r"(a[0]), "r"(a[1]), "r"(a[2]), "r"(a[3]), "r"(b0), "r"(b1));
}
__device__ __forceinline__ void cpasync16(uint32_t saddr, const void* g) {
    asm volatile("cp.async.cg.shared.global [%0], [%1], 16;" :: "r"(saddr), "l"(g));
}
#define CP_COMMIT() asm volatile("cp.async.commit_group;" ::: "memory")
#define CP_WAIT(N)  asm volatile("cp.async.wait_group %0;" :: "n"(N) : "memory")

// ================= setup =================
__device__ __forceinline__ void fold_single(int t0, int stride,
        const float* __restrict__ W, const float* __restrict__ g, const float* __restrict__ v,
        __half* wd, int C, int Kdst, int Ksrc, int Koff) {
    for (int idx = t0; idx < C * Kdst; idx += stride) {
        int c = idx / Kdst, k = idx - c * Kdst;
        float s = g[c] * rsqrtf(v[c] + EPSF);
        wd[idx] = __float2half_rn(s * W[(size_t)c * Ksrc + Koff + k]);
    }
}
__device__ __forceinline__ void fold_bias(int t0, int stride,
        const float* b, const float* g, const float* be, const float* m, const float* v,
        float* bf, int C) {
    for (int i = t0; i < C; i += stride) {
        float s = g[i] * rsqrtf(v[i] + EPSF);
        bf[i] = s * b[i] + be[i] - s * m[i];
    }
}

__global__ void setup_kernel(const int* __restrict__ npts,
    const float* W1, const float* b1, const float* g1, const float* be1, const float* m1, const float* v1,
    const float* W2, const float* b2, const float* g2, const float* be2, const float* m2, const float* v2,
    const float* W3, const float* b3, const float* g3, const float* be3, const float* m3, const float* v3,
    const float* W4, const float* b4, const float* g4, const float* be4, const float* m4, const float* v4) {
    const int stride = gridDim.x * blockDim.x;
    const int t0 = blockIdx.x * blockDim.x + threadIdx.x;

    for (int c = t0; c < 128; c += stride) {
        float s = g1[c] * rsqrtf(v1[c] + EPSF);
        d_W1c[c * 4 + 0] = s * W1[c * 3 + 0];
        d_W1c[c * 4 + 1] = s * W1[c * 3 + 1];
        d_W1c[c * 4 + 2] = s * W1[c * 3 + 2];
        d_W1c[c * 4 + 3] = s * b1[c] + be1[c] - s * m1[c];
    }
    fold_single(t0, stride, W2, g2, v2, d_w2, 256,  128, 128, 0);
    fold_single(t0, stride, W3, g3, v3, d_w3, 512,  256, 512, 256);
    fold_single(t0, stride, W4, g4, v4, d_w4, 1024, 512, 512, 0);
    fold_bias(t0, stride, b2, g2, be2, m2, v2, d_b2f, 256);
    fold_bias(t0, stride, b3, g3, be3, m3, v3, d_b3f, 512);
    fold_bias(t0, stride, b4, g4, be4, m4, v4, d_b4f, 1024);

    int cum[BSEG];
    {
        int a = 0;
        #pragma unroll
        for (int t = 0; t < BSEG; t++) { a += __ldg(&npts[t]); cum[t] = a; }
    }
    for (int j = t0; j < NPTS; j += stride) {
        int s = 0;
        #pragma unroll
        for (int t = 0; t < BSEG - 1; t++) s += (j >= cum[t]);
        d_seg[j] = s;
    }
    for (int i = t0; i < BSEG * 1024; i += stride) d_vkey[i] = 0u;
    for (int i = t0; i < BSEG * 256;  i += stride) d_gkey[i] = 0u;
}

__global__ void fin_v_kernel(float* __restrict__ out) {
    int i = blockIdx.x * blockDim.x + threadIdx.x;
    if (i < BSEG * 1024) out[i] = key2f(d_vkey[i]);
}
__global__ void k_u_kernel(const float* __restrict__ W3,
                           const float* __restrict__ g3,
                           const float* __restrict__ v3) {
    int w = (blockIdx.x * blockDim.x + threadIdx.x) >> 5;
    int lane = threadIdx.x & 31;
    if (w >= 512 * BSEG) return;
    int m = w >> 4, s = w & 15;
    float acc = 0.0f;
    for (int r = lane; r < 256; r += 32)
        acc += W3[(size_t)m * 512 + r] * key2f(d_gkey[s * 256 + r]);
    #pragma unroll
    for (int o = 16; o; o >>= 1) acc += __shfl_xor_sync(0xffffffffu, acc, o);
    if (lane == 0) d_u[m * BSEG + s] = g3[m] * rsqrtf(v3[m] + EPSF) * acc;
}

// ================= mma.sync GEMM (8 warps/CTA 32x64 tiles, 2 CTAs/SM = 16 warps/SM) =================
// CTA: 128 pts x 128 chans; 8 warps 4(m) x 2(n); per-warp 32x64.
// K chunks of 64; 3 stages; swizzled 128B rows. 98 KB smem/CTA -> 2 CTAs/SM.
// CFG0 fuses layer-1.
#define ROWB    128
#define ATILE   (128 * ROWB)          // 16384
#define BTILE   (128 * ROWB)          // 16384
#define STAGEB  (ATILE + BTILE)       // 32768
#define NSTAGE  3
#define RED_OFF (NSTAGE * STAGEB)     // float red[8][64] = 2048 B
#define MM_SMEM (RED_OFF + 2048)      // 100352 B

template<int CFG>
__global__ void __launch_bounds__(256, 2) mm_kernel(const float* __restrict__ xg) {
    constexpr int K    = (CFG == 0) ? 128 : (CFG == 1) ? 256 : 512;
    constexpr int MOUT = (CFG == 0) ? 256 : (CFG == 1) ? 512 : 1024;
    constexpr int KC   = K / 64;
    constexpr bool SEGMAX = (CFG != 1);
    constexpr bool STORE  = (CFG != 2);
    constexpr bool FUSE1  = (CFG == 0);

    const __half* __restrict__ Ain = (CFG == 1) ? d_a2 : d_a3;   // unused for CFG0
    const __half* __restrict__ Bw  = (CFG == 0) ? d_w2 : (CFG == 1) ? d_w3 : d_w4;
    const float* __restrict__ bias = (CFG == 0) ? d_b2f : (CFG == 1) ? d_b3f : d_b4f;
    __half* Oa = (CFG == 0) ? d_a2 : d_a3;
    unsigned* key = (CFG == 0) ? d_gkey : d_vkey;

    extern __shared__ char smem[];
    const uint32_t sb = smem_to_u32(smem);
    const int tid = threadIdx.x, wid = tid >> 5, lane = tid & 31;
    const int wm = wid & 3, wn = wid >> 2;
    const int n0 = blockIdx.x * 128;
    const int pt0 = blockIdx.y * 128;

    float acc[2][8][4];
    #pragma unroll
    for (int mi = 0; mi < 2; mi++)
        #pragma unroll
        for (int nt = 0; nt < 8; nt++)
            #pragma unroll
            for (int q = 0; q < 4; q++) acc[mi][nt][q] = 0.0f;

    auto load_B = [&](int kc, int buf) {
        const int k0 = kc * 64;
        const uint32_t base = sb + (uint32_t)buf * STAGEB;
        #pragma unroll
        for (int i = 0; i < 4; i++) {
            int idx = i * 256 + tid;              // 0..1023
            int row = idx >> 3, c8 = idx & 7;
            cpasync16(base + ATILE + SW128((uint32_t)(row * ROWB + c8 * 16)),
                      Bw + (size_t)(n0 + row) * K + k0 + c8 * 8);
        }
    };
    auto load_chunk = [&](int kc, int buf) {
        const int k0 = kc * 64;
        const uint32_t base = sb + (uint32_t)buf * STAGEB;
        #pragma unroll
        for (int i = 0; i < 4; i++) {
            int idx = i * 256 + tid;
            int row = idx >> 3, c8 = idx & 7;
            cpasync16(base + SW128((uint32_t)(row * ROWB + c8 * 16)),
                      Ain + (size_t)(pt0 + row) * K + k0 + c8 * 8);
        }
        load_B(kc, buf);
        CP_COMMIT();
    };

    auto compute = [&](int buf) {
        const uint32_t ab = sb + (uint32_t)buf * STAGEB;
        const uint32_t bbB = ab + ATILE;
        #pragma unroll
        for (int kk = 0; kk < 4; kk++) {
            const uint32_t col = (uint32_t)((lane >> 4) * 16 + kk * 32);  // bytes
            uint32_t a_f[2][4];
            #pragma unroll
            for (int mi = 0; mi < 2; mi++) {
                uint32_t row = (uint32_t)(wm * 32 + mi * 16 + (lane & 15));
                ldsm4(a_f[mi], ab + SW128(row * ROWB + col));
            }
            #pragma unroll
            for (int nt4 = 0; nt4 < 4; nt4++) {
                uint32_t row = (uint32_t)(wn * 64 + nt4 * 16 + (lane & 15));
                uint32_t b_f[4];
                ldsm4(b_f, bbB + SW128(row * ROWB + col));
                #pragma unroll
                for (int mi = 0; mi < 2; mi++) {
                    mma16816(acc[mi][nt4 * 2 + 0], a_f[mi], b_f[0], b_f[2]);
                    mma16816(acc[mi][nt4 * 2 + 1], a_f[mi], b_f[1], b_f[3]);
                }
            }
        }
    };

    if (FUSE1) {
        load_B(0, 0); CP_COMMIT();
        load_B(1, 1); CP_COMMIT();
        // layer-1: 2 threads per point; each handles 64 channels -> one K-chunk's A row half
        {
            const int pt = pt0 + (tid >> 1);
            const int half = tid & 1;             // which K-chunk (channels 0-63 / 64-127)
            const int row = tid >> 1;
            const float x0 = xg[pt], x1 = xg[NPTS + pt], x2 = xg[2 * NPTS + pt];
            #pragma unroll
            for (int g = 0; g < 8; g++) {         // 8 groups of 8 channels
                __half2 h2[4];
                #pragma unroll
                for (int q = 0; q < 4; q++) {
                    #pragma unroll
                    for (int r = 0; r < 2; r++) {
                        const int c = (half * 8 + g) * 8 + q * 2 + r;
                        const float* w = &d_W1c[c * 4];
                        float v = fmaxf(__ldg(&w[3]) + __ldg(&w[0]) * x0
                                      + __ldg(&w[1]) * x1 + __ldg(&w[2]) * x2, 0.0f);
                        if (r == 0) h2[q].x = __float2half_rn(v);
                        else        h2[q].y = __float2half_rn(v);
                    }
                }
                uint32_t off = (uint32_t)half * STAGEB
                             + SW128((uint32_t)(row * ROWB + g * 16));
                *reinterpret_cast<uint4*>(smem + off) = *reinterpret_cast<uint4*>(h2);
            }
        }
    } else {
        load_chunk(0, 0);
        if (KC > 1) load_chunk(1, 1);
    }

    #pragma unroll 1
    for (int kc = 0; kc < KC; kc++) {
        if (kc + 1 < KC) { CP_WAIT(1); } else { CP_WAIT(0); }
        __syncthreads();
        if (!FUSE1 && kc + 2 < KC) load_chunk(kc + 2, (kc + 2) % NSTAGE);
        compute(FUSE1 ? kc : (kc % NSTAGE));
    }

    // ---- epilogue ----
    int ptr_[4], sg[4];
    #pragma unroll
    for (int mi = 0; mi < 2; mi++)
        #pragma unroll
        for (int h = 0; h < 2; h++) {
            int p = pt0 + wm * 32 + mi * 16 + (lane >> 2) + h * 8;
            ptr_[mi * 2 + h] = p;
            sg[mi * 2 + h] = d_seg[p];
        }
    const int cbase = n0 + wn * 64 + (lane & 3) * 2;

    #pragma unroll
    for (int mi = 0; mi < 2; mi++) {
        #pragma unroll
        for (int h = 0; h < 2; h++) {
            const int p = ptr_[mi * 2 + h];
            const int seg = sg[mi * 2 + h];
            #pragma unroll
            for (int nt = 0; nt < 8; nt++) {
                const int c = cbase + nt * 8;
                float v0 = acc[mi][nt][h * 2 + 0] + __ldg(&bias[c]);
                float v1 = acc[mi][nt][h * 2 + 1] + __ldg(&bias[c + 1]);
                if (CFG == 1) {
                    v0 = fmaxf(v0 + d_u[c * BSEG + seg], 0.0f);
                    v1 = fmaxf(v1 + d_u[(c + 1) * BSEG + seg], 0.0f);
                }
                acc[mi][nt][h * 2 + 0] = v0;
                acc[mi][nt][h * 2 + 1] = v1;
                if (STORE) {
                    __half2 hh;
                    hh.x = __float2half_rn(v0);
                    hh.y = __float2half_rn(v1);
                    *reinterpret_cast<uint32_t*>(&Oa[(size_t)p * MOUT + c]) =
                        *reinterpret_cast<uint32_t*>(&hh);
                }
            }
        }
    }

    if (SEGMAX) {
        float* red = reinterpret_cast<float*>(smem + RED_OFF);
        const int s_lo = d_seg[pt0], s_hi = d_seg[pt0 + 127];
        const int np = (s_lo == s_hi) ? 1 : 2;
        for (int pass = 0; pass < np; pass++) {
            const int s = pass ? s_hi : s_lo;
            float cm[8][2];
            #pragma unroll
            for (int nt = 0; nt < 8; nt++) { cm[nt][0] = -3.402823466e38f; cm[nt][1] = -3.402823466e38f; }
            #pragma unroll
            for (int mi = 0; mi < 2; mi++)
                #pragma unroll
                for (int h = 0; h < 2; h++)
                    if (sg[mi * 2 + h] == s) {
                        #pragma unroll
                        for (int nt = 0; nt < 8; nt++) {
                            cm[nt][0] = fmaxf(cm[nt][0], acc[mi][nt][h * 2 + 0]);
                            cm[nt][1] = fmaxf(cm[nt][1], acc[mi][nt][h * 2 + 1]);
                        }
                    }
            #pragma unroll
            for (int o = 4; o < 32; o <<= 1)
                #pragma unroll
                for (int nt = 0; nt < 8; nt++) {
                    cm[nt][0] = fmaxf(cm[nt][0], __shfl_xor_sync(0xffffffffu, cm[nt][0], o));
                    cm[nt][1] = fmaxf(cm[nt][1], __shfl_xor_sync(0xffffffffu, cm[nt][1], o));
                }
            __syncthreads();
            if ((lane >> 2) == 0) {
                #pragma unroll
                for (int nt = 0; nt < 8; nt++) {
                    red[wid * 64 + nt * 8 + (lane & 3) * 2 + 0] = cm[nt][0];
                    red[wid * 64 + nt * 8 + (lane & 3) * 2 + 1] = cm[nt][1];
                }
            }
            __syncthreads();
            if ((wid & 3) == 0) {   // wid 0 (wn=0), wid 4 (wn=1)
                const int wgrp = wid >> 2;
                #pragma unroll
                for (int cc = 0; cc < 2; cc++) {
                    const int col = lane * 2 + cc;
                    float m = red[(wgrp * 4 + 0) * 64 + col];
                    #pragma unroll
                    for (int w = 1; w < 4; w++)
                        m = fmaxf(m, red[(wgrp * 4 + w) * 64 + col]);
                    atomicMax(&key[s * MOUT + n0 + wgrp * 64 + col], f2key(m));
                }
            }
        }
    }
}

// ================= launch =================
extern "C" void kernel_launch(void* const* d_in, const int* in_sizes, int n_in,
                              void* d_out, int out_size) {
    const float* x    = (const float*)d_in[0];
    const int*   npts = (const int*  )d_in[1];
    const float *W1 = (const float*)d_in[2],  *b1 = (const float*)d_in[3],
                *g1 = (const float*)d_in[4],  *be1= (const float*)d_in[5],
                *m1 = (const float*)d_in[6],  *v1 = (const float*)d_in[7];
    const float *W2 = (const float*)d_in[8],  *b2 = (const float*)d_in[9],
                *g2 = (const float*)d_in[10], *be2= (const float*)d_in[11],
                *m2 = (const float*)d_in[12], *v2 = (const float*)d_in[13];
    const float *W3 = (const float*)d_in[14], *b3 = (const float*)d_in[15],
                *g3 = (const float*)d_in[16], *be3= (const float*)d_in[17],
                *m3 = (const float*)d_in[18], *v3 = (const float*)d_in[19];
    const float *W4 = (const float*)d_in[20], *b4 = (const float*)d_in[21],
                *g4 = (const float*)d_in[22], *be4= (const float*)d_in[23],
                *m4 = (const float*)d_in[24], *v4 = (const float*)d_in[25];

    cudaFuncSetAttribute(mm_kernel<0>, cudaFuncAttributeMaxDynamicSharedMemorySize, MM_SMEM);
    cudaFuncSetAttribute(mm_kernel<1>, cudaFuncAttributeMaxDynamicSharedMemorySize, MM_SMEM);
    cudaFuncSetAttribute(mm_kernel<2>, cudaFuncAttributeMaxDynamicSharedMemorySize, MM_SMEM);

    setup_kernel<<<512, 256>>>(npts,
        W1, b1, g1, be1, m1, v1,  W2, b2, g2, be2, m2, v2,
        W3, b3, g3, be3, m3, v3,  W4, b4, g4, be4, m4, v4);

    mm_kernel<0><<<dim3(2, NPTS / 128), 256, MM_SMEM>>>(x);  // #2: f (+g segmax), layer1 fused
    k_u_kernel<<<1024, 256>>>(W3, g3, v3);                   // #3
    mm_kernel<1><<<dim3(4, NPTS / 128), 256, MM_SMEM>>>(x);  // #4: h3  <- ncu captures this
    mm_kernel<2><<<dim3(8, NPTS / 128), 256, MM_SMEM>>>(x);  // #5: v segmax
    fin_v_kernel<<<64, 256>>>((float*)d_out);                // #6
}